// round 13
// baseline (speedup 1.0000x reference)
#include <cuda_runtime.h>
#include <cuda_bf16.h>
#include <cstdint>

#define Bc  4
#define LXc 384
#define LYc 384
#define Hc  256
#define Fc  512

// scratch (allocation-free rule: __device__ globals)
__device__ float  g_Xp[Bc * LXc * Hc];     // x @ Wm^T (fp32, for score)
__device__ float  g_Yp[Bc * LYc * Hc];     // y @ Wm^T
__device__ float  g_S [Bc * LYc * LXc];    // raw scores
__device__ ushort g_xh[Bc * LXc * Fc], g_xl[Bc * LXc * Fc];   // x  hi/lo bf16
__device__ ushort g_yh[Bc * LYc * Fc], g_yl[Bc * LYc * Fc];   // y  hi/lo
__device__ ushort g_Wh[Hc * Fc],       g_Wl[Hc * Fc];         // Wm hi/lo
__device__ ushort g_xTh[Bc * Fc * LXc], g_xTl[Bc * Fc * LXc]; // xT hi/lo
__device__ ushort g_Ph[Bc * LYc * LXc], g_Pl[Bc * LYc * LXc]; // softmax P hi/lo

__device__ __forceinline__ float tanh_fast(float x) {
    float r; asm("tanh.approx.f32 %0, %1;" : "=f"(r) : "f"(x)); return r;
}
__device__ __forceinline__ float ex2_fast(float x) {
    float r; asm("ex2.approx.f32 %0, %1;" : "=f"(r) : "f"(x)); return r;
}
__device__ __forceinline__ uint32_t smem_u32(const void* p) {
    uint32_t a;
    asm("{ .reg .u64 t; cvta.to.shared.u64 t, %1; cvt.u32.u64 %0, t; }"
        : "=r"(a) : "l"(p));
    return a;
}
__device__ __forceinline__ uint32_t packbf(float lo, float hi) {
    uint32_t r;
    asm("cvt.rn.bf16x2.f32 %0, %1, %2;" : "=r"(r) : "f"(hi), "f"(lo));
    return r;
}
__device__ __forceinline__ uint32_t packres(uint32_t h, float lo, float hi) {
    float fl = __uint_as_float(h << 16);
    float fh = __uint_as_float(h & 0xffff0000u);
    return packbf(lo - fl, hi - fh);
}
__device__ __forceinline__ void ldm4(uint32_t* r, uint32_t a) {
    asm volatile("ldmatrix.sync.aligned.m8n8.x4.shared.b16 {%0,%1,%2,%3}, [%4];"
                 : "=r"(r[0]), "=r"(r[1]), "=r"(r[2]), "=r"(r[3]) : "r"(a));
}
__device__ __forceinline__ void mma16816(float* c, const uint32_t* a,
                                         uint32_t b0, uint32_t b1) {
    asm volatile(
        "mma.sync.aligned.m16n8k16.row.col.f32.bf16.bf16.f32 "
        "{%0,%1,%2,%3}, {%4,%5,%6,%7}, {%8,%9}, {%0,%1,%2,%3};"
        : "+f"(c[0]), "+f"(c[1]), "+f"(c[2]), "+f"(c[3])
        : "r"(a[0]), "r"(a[1]), "r"(a[2]), "r"(a[3]), "r"(b0), "r"(b1));
}

// ---------------------------------------------------------------------------
// HMMA GEMM on pre-split bf16 hi/lo operands (global -> smem -> ldmatrix).
// C[64,64] = A[64,K] @ B[64,K]^T, 3-product hi/lo, fp32 accum.
// 128 threads (4 warps, 32x32 each). K multiple of 32.
// MMA/ldmatrix structure identical to the validated round-12 kernel.
// ---------------------------------------------------------------------------
__device__ void gemm_mma_pre(const ushort* __restrict__ Ah,
                             const ushort* __restrict__ Al, int lda,
                             const ushort* __restrict__ Bh,
                             const ushort* __restrict__ Bl, int ldb,
                             float* __restrict__ C, int ldc, int K)
{
    __shared__ __align__(16) ushort AHs[2][64 * 40], ALs[2][64 * 40];
    __shared__ __align__(16) ushort BHs[2][64 * 40], BLs[2][64 * 40];

    const int tid = threadIdx.x, wid = tid >> 5, lane = tid & 31;
    const int wm = (wid >> 1) * 32, wn = (wid & 1) * 32;
    const int crow = tid >> 1, ckb = (tid & 1) * 16;
    const int cidx = crow * 40 + ckb;

    const ushort* pAh = Ah + crow * lda + ckb;
    const ushort* pAl = Al + crow * lda + ckb;
    const ushort* pBh = Bh + crow * ldb + ckb;
    const ushort* pBl = Bl + crow * ldb + ckb;

    float c[2][4][4];
    #pragma unroll
    for (int i = 0; i < 2; i++)
        #pragma unroll
        for (int j = 0; j < 4; j++)
            #pragma unroll
            for (int q = 0; q < 4; q++) c[i][j][q] = 0.f;

    // prologue: chunk 0 -> buf 0
    *(uint4*)&AHs[0][cidx]     = *(const uint4*)pAh;
    *(uint4*)&AHs[0][cidx + 8] = *(const uint4*)(pAh + 8);
    *(uint4*)&ALs[0][cidx]     = *(const uint4*)pAl;
    *(uint4*)&ALs[0][cidx + 8] = *(const uint4*)(pAl + 8);
    *(uint4*)&BHs[0][cidx]     = *(const uint4*)pBh;
    *(uint4*)&BHs[0][cidx + 8] = *(const uint4*)(pBh + 8);
    *(uint4*)&BLs[0][cidx]     = *(const uint4*)pBl;
    *(uint4*)&BLs[0][cidx + 8] = *(const uint4*)(pBl + 8);
    __syncthreads();

    const int nch = K >> 5;
    int buf = 0;
    for (int ch = 0; ch < nch; ch++) {
        uint4 rah0, rah1, ral0, ral1, rbh0, rbh1, rbl0, rbl1;
        if (ch + 1 < nch) {
            const int nk = (ch + 1) * 32;
            rah0 = *(const uint4*)(pAh + nk); rah1 = *(const uint4*)(pAh + nk + 8);
            ral0 = *(const uint4*)(pAl + nk); ral1 = *(const uint4*)(pAl + nk + 8);
            rbh0 = *(const uint4*)(pBh + nk); rbh1 = *(const uint4*)(pBh + nk + 8);
            rbl0 = *(const uint4*)(pBl + nk); rbl1 = *(const uint4*)(pBl + nk + 8);
        }

        #pragma unroll
        for (int ks = 0; ks < 2; ks++) {
            uint32_t aHf[2][4], aLf[2][4], bHf[2][4], bLf[2][4];
            #pragma unroll
            for (int mt = 0; mt < 2; mt++) {
                const int row = wm + mt * 16 + (lane & 15);
                const int kc  = ks * 16 + (lane >> 4) * 8;
                const int off = row * 40 + kc;
                ldm4(aHf[mt], smem_u32(&AHs[buf][off]));
                ldm4(aLf[mt], smem_u32(&ALs[buf][off]));
            }
            #pragma unroll
            for (int g = 0; g < 2; g++) {
                const int row = wn + g * 16 + ((lane >> 4) << 3) + (lane & 7);
                const int kc  = ks * 16 + ((lane >> 3) & 1) * 8;
                const int off = row * 40 + kc;
                ldm4(bHf[g], smem_u32(&BHs[buf][off]));
                ldm4(bLf[g], smem_u32(&BLs[buf][off]));
            }
            #pragma unroll
            for (int mt = 0; mt < 2; mt++)
                #pragma unroll
                for (int g = 0; g < 2; g++)
                    #pragma unroll
                    for (int h = 0; h < 2; h++) {
                        float* cf = c[mt][g * 2 + h];
                        mma16816(cf, aHf[mt], bHf[g][2*h], bHf[g][2*h+1]);
                        mma16816(cf, aLf[mt], bHf[g][2*h], bHf[g][2*h+1]);
                        mma16816(cf, aHf[mt], bLf[g][2*h], bLf[g][2*h+1]);
                    }
        }

        if (ch + 1 < nch) {
            const int nb = buf ^ 1;
            *(uint4*)&AHs[nb][cidx]     = rah0;
            *(uint4*)&AHs[nb][cidx + 8] = rah1;
            *(uint4*)&ALs[nb][cidx]     = ral0;
            *(uint4*)&ALs[nb][cidx + 8] = ral1;
            *(uint4*)&BHs[nb][cidx]     = rbh0;
            *(uint4*)&BHs[nb][cidx + 8] = rbh1;
            *(uint4*)&BLs[nb][cidx]     = rbl0;
            *(uint4*)&BLs[nb][cidx + 8] = rbl1;
            __syncthreads();
            buf = nb;
        }
    }

    #pragma unroll
    for (int mt = 0; mt < 2; mt++) {
        const int r0 = wm + mt * 16 + (lane >> 2);
        #pragma unroll
        for (int nt = 0; nt < 4; nt++) {
            const int cc = wn + nt * 8 + (lane & 3) * 2;
            float* p = C + r0 * ldc + cc;
            *(float2*)p             = make_float2(c[mt][nt][0], c[mt][nt][1]);
            *(float2*)(p + 8 * ldc) = make_float2(c[mt][nt][2], c[mt][nt][3]);
        }
    }
}

// ---------------------------------------------------------------------------
// Kernel A: split x / y / Wm into bf16 hi/lo in global memory (once).
// ---------------------------------------------------------------------------
__global__ __launch_bounds__(256) void conv_split_kernel(
    const float* __restrict__ x, const float* __restrict__ y,
    const float* __restrict__ W)
{
    const int NX4 = Bc * LXc * Fc / 4;
    const int NY4 = Bc * LYc * Fc / 4;
    const int NW4 = Hc * Fc / 4;
    int i4 = blockIdx.x * 256 + threadIdx.x;
    const float* src; ushort* dh; ushort* dl; int o4;
    if (i4 < NX4)            { src = x; dh = g_xh; dl = g_xl; o4 = i4; }
    else if (i4 < NX4 + NY4) { src = y; dh = g_yh; dl = g_yl; o4 = i4 - NX4; }
    else if (i4 < NX4 + NY4 + NW4)
                             { src = W; dh = g_Wh; dl = g_Wl; o4 = i4 - NX4 - NY4; }
    else return;
    float4 v = ((const float4*)src)[o4];
    uint32_t h0 = packbf(v.x, v.y), h1 = packbf(v.z, v.w);
    uint32_t l0 = packres(h0, v.x, v.y), l1 = packres(h1, v.z, v.w);
    ((uint2*)dh)[o4] = make_uint2(h0, h1);
    ((uint2*)dl)[o4] = make_uint2(l0, l1);
}

// ---------------------------------------------------------------------------
// Kernel B: transpose x -> bf16 hi/lo xT[b][f][l]
// ---------------------------------------------------------------------------
__global__ __launch_bounds__(256) void transpose_x_kernel(const float* __restrict__ x)
{
    __shared__ float t[32][33];
    const int b  = blockIdx.z;
    const int f0 = blockIdx.x * 32;
    const int l0 = blockIdx.y * 32;
    const int tx = threadIdx.x & 31;
    const int ty = threadIdx.x >> 5;

    #pragma unroll
    for (int i = ty; i < 32; i += 8)
        t[i][tx] = x[(b * LXc + l0 + i) * Fc + f0 + tx];
    __syncthreads();
    #pragma unroll
    for (int i = ty; i < 32; i += 8) {
        float v = t[tx][i];
        __nv_bfloat16 h = __float2bfloat16(v);
        __nv_bfloat16 l = __float2bfloat16(v - __bfloat162float(h));
        const int idx = (b * Fc + f0 + i) * LXc + l0 + tx;
        g_xTh[idx] = __bfloat16_as_ushort(h);
        g_xTl[idx] = __bfloat16_as_ushort(l);
    }
}

// ---------------------------------------------------------------------------
// Kernel 1: proj.  Out[r,h] = sum_f In[r,f]*W[h,f].  K=512.
// grid (Hc/64=4, 1536/64=24, 2)
// ---------------------------------------------------------------------------
__global__ __launch_bounds__(128) void proj_mma_kernel()
{
    const ushort* Ah = blockIdx.z ? g_yh : g_xh;
    const ushort* Al = blockIdx.z ? g_yl : g_xl;
    float*        Out = blockIdx.z ? g_Yp : g_Xp;
    gemm_mma_pre(Ah + blockIdx.y * 64 * Fc, Al + blockIdx.y * 64 * Fc, Fc,
                 g_Wh + blockIdx.x * 64 * Fc, g_Wl + blockIdx.x * 64 * Fc, Fc,
                 Out + blockIdx.y * 64 * Hc + blockIdx.x * 64, Hc, Fc);
}

// ---------------------------------------------------------------------------
// Kernel 4: outgemm.  qtm[b,y,f] = sum_l P[b,y,l]*xT[b,f,l].  K=384.
// grid (Fc/64=8, LYc/64=6, Bc)
// ---------------------------------------------------------------------------
__global__ __launch_bounds__(128) void outgemm_mma_kernel(float* __restrict__ out)
{
    const int b = blockIdx.z;
    gemm_mma_pre(g_Ph  + (b * LYc + blockIdx.y * 64) * LXc,
                 g_Pl  + (b * LYc + blockIdx.y * 64) * LXc, LXc,
                 g_xTh + (b * Fc + blockIdx.x * 64) * LXc,
                 g_xTl + (b * Fc + blockIdx.x * 64) * LXc, LXc,
                 out + (b * LYc + blockIdx.y * 64) * Fc + blockIdx.x * 64,
                 Fc, LXc);
}

// ---------------------------------------------------------------------------
// Kernel 2: GEMM-shaped tanh-score (MUFU-bound, at its floor — unchanged).
// ---------------------------------------------------------------------------
__global__ __launch_bounds__(256) void score_tile_kernel(const float* __restrict__ vm)
{
    const int b  = blockIdx.z;
    const int y0 = blockIdx.y * 64;
    const int l0 = blockIdx.x * 64;

    __shared__ float Ys[16][68];
    __shared__ float Xs[16][68];
    __shared__ float Vs[Hc];

    const int tid = threadIdx.x;
    for (int i = tid; i < Hc; i += 256) Vs[i] = vm[i];

    const int lrow = tid >> 2;
    const int f4   = (tid & 3) * 4;
    const int tx   = tid & 15;
    const int ty   = tid >> 4;

    const float* Yb = g_Yp + (b * LYc + y0) * Hc;
    const float* Xb = g_Xp + (b * LXc + l0) * Hc;

    float acc[4][4] = {};

    for (int k0 = 0; k0 < Hc; k0 += 16) {
        float4 av = *(const float4*)&Yb[lrow * Hc + k0 + f4];
        float4 bv = *(const float4*)&Xb[lrow * Hc + k0 + f4];
        __syncthreads();
        Ys[f4 + 0][lrow] = av.x; Ys[f4 + 1][lrow] = av.y;
        Ys[f4 + 2][lrow] = av.z; Ys[f4 + 3][lrow] = av.w;
        Xs[f4 + 0][lrow] = bv.x; Xs[f4 + 1][lrow] = bv.y;
        Xs[f4 + 2][lrow] = bv.z; Xs[f4 + 3][lrow] = bv.w;
        __syncthreads();

        #pragma unroll
        for (int kk = 0; kk < 16; kk++) {
            const float v = Vs[k0 + kk];
            float4 yv = *(const float4*)&Ys[kk][ty * 4];
            float4 xv = *(const float4*)&Xs[kk][tx * 4];
            float t00 = tanh_fast(xv.x - yv.x);
            float t01 = tanh_fast(xv.y - yv.x);
            float t02 = tanh_fast(xv.z - yv.x);
            float t03 = tanh_fast(xv.w - yv.x);
            float t10 = tanh_fast(xv.x - yv.y);
            float t11 = tanh_fast(xv.y - yv.y);
            float t12 = tanh_fast(xv.z - yv.y);
            float t13 = tanh_fast(xv.w - yv.y);
            float t20 = tanh_fast(xv.x - yv.z);
            float t21 = tanh_fast(xv.y - yv.z);
            float t22 = tanh_fast(xv.z - yv.z);
            float t23 = tanh_fast(xv.w - yv.z);
            float t30 = tanh_fast(xv.x - yv.w);
            float t31 = tanh_fast(xv.y - yv.w);
            float t32 = tanh_fast(xv.z - yv.w);
            float t33 = tanh_fast(xv.w - yv.w);
            acc[0][0] = fmaf(v, t00, acc[0][0]);
            acc[0][1] = fmaf(v, t01, acc[0][1]);
            acc[0][2] = fmaf(v, t02, acc[0][2]);
            acc[0][3] = fmaf(v, t03, acc[0][3]);
            acc[1][0] = fmaf(v, t10, acc[1][0]);
            acc[1][1] = fmaf(v, t11, acc[1][1]);
            acc[1][2] = fmaf(v, t12, acc[1][2]);
            acc[1][3] = fmaf(v, t13, acc[1][3]);
            acc[2][0] = fmaf(v, t20, acc[2][0]);
            acc[2][1] = fmaf(v, t21, acc[2][1]);
            acc[2][2] = fmaf(v, t22, acc[2][2]);
            acc[2][3] = fmaf(v, t23, acc[2][3]);
            acc[3][0] = fmaf(v, t30, acc[3][0]);
            acc[3][1] = fmaf(v, t31, acc[3][1]);
            acc[3][2] = fmaf(v, t32, acc[3][2]);
            acc[3][3] = fmaf(v, t33, acc[3][3]);
        }
    }

    float* Sb = g_S + (b * LYc + y0) * LXc + l0;
    #pragma unroll
    for (int i = 0; i < 4; i++) {
        float4 st = make_float4(acc[i][0], acc[i][1], acc[i][2], acc[i][3]);
        *(float4*)&Sb[(ty * 4 + i) * LXc + tx * 4] = st;
    }
}

// ---------------------------------------------------------------------------
// Kernel 3: softmax over l; writes P as bf16 hi/lo directly. Warp per row.
// ---------------------------------------------------------------------------
__global__ __launch_bounds__(256) void softmax_kernel()
{
    const int b    = blockIdx.y;
    const int y    = blockIdx.x * 8 + (threadIdx.x >> 5);
    const int lane = threadIdx.x & 31;

    const float* Srow = g_S + (b * LYc + y) * LXc;
    float v[12];
    float mx = -1e30f;
    #pragma unroll
    for (int j = 0; j < 12; j++) {
        v[j] = Srow[lane + 32 * j];
        mx = fmaxf(mx, v[j]);
    }
    #pragma unroll
    for (int o = 16; o; o >>= 1)
        mx = fmaxf(mx, __shfl_xor_sync(0xffffffffu, mx, o));
    float sum = 0.f;
    #pragma unroll
    for (int j = 0; j < 12; j++) {
        v[j] = ex2_fast((v[j] - mx) * 1.4426950408889634f);
        sum += v[j];
    }
    #pragma unroll
    for (int o = 16; o; o >>= 1)
        sum += __shfl_xor_sync(0xffffffffu, sum, o);
    float inv = 1.0f / sum;

    const int rbase = (b * LYc + y) * LXc;
    #pragma unroll
    for (int j = 0; j < 12; j++) {
        float p = v[j] * inv;
        __nv_bfloat16 h = __float2bfloat16(p);
        __nv_bfloat16 l = __float2bfloat16(p - __bfloat162float(h));
        g_Ph[rbase + lane + 32 * j] = __bfloat16_as_ushort(h);
        g_Pl[rbase + lane + 32 * j] = __bfloat16_as_ushort(l);
    }
}

// ---------------------------------------------------------------------------
extern "C" void kernel_launch(void* const* d_in, const int* in_sizes, int n_in,
                              void* d_out, int out_size)
{
    const float* x  = (const float*)d_in[0];
    const float* y  = (const float*)d_in[1];
    const float* Wm = (const float*)d_in[2];
    const float* vm = (const float*)d_in[3];
    float* out = (float*)d_out;

    const int NTOT4 = (Bc * LXc * Fc + Bc * LYc * Fc + Hc * Fc) / 4;
    conv_split_kernel <<<(NTOT4 + 255) / 256, 256>>>(x, y, Wm);
    transpose_x_kernel<<<dim3(Fc / 32, LXc / 32, Bc), 256>>>(x);
    proj_mma_kernel   <<<dim3(Hc / 64, (LXc * Bc) / 64, 2), 128>>>();
    score_tile_kernel <<<dim3(LXc / 64, LYc / 64, Bc), 256>>>(vm);
    softmax_kernel    <<<dim3(LYc / 8, Bc), 256>>>();
    outgemm_mma_kernel<<<dim3(Fc / 64, LYc / 64, Bc), 128>>>(out);
}

// round 14
// speedup vs baseline: 1.0453x; 1.0453x over previous
#include <cuda_runtime.h>
#include <cuda_bf16.h>
#include <cstdint>

#define Bc  4
#define LXc 384
#define LYc 384
#define Hc  256
#define Fc  512

// scratch (allocation-free rule: __device__ globals)
__device__ float  g_Xp[Bc * LXc * Hc];     // x @ Wm^T (fp32, for score)
__device__ float  g_Yp[Bc * LYc * Hc];     // y @ Wm^T
__device__ float  g_S [Bc * LYc * LXc];    // raw scores
__device__ ushort g_xh[Bc * LXc * Fc], g_xl[Bc * LXc * Fc];   // x  hi/lo bf16
__device__ ushort g_yh[Bc * LYc * Fc], g_yl[Bc * LYc * Fc];   // y  hi/lo
__device__ ushort g_Wh[Hc * Fc],       g_Wl[Hc * Fc];         // Wm hi/lo
__device__ ushort g_xTh[Bc * Fc * LXc], g_xTl[Bc * Fc * LXc]; // xT hi/lo
__device__ ushort g_Ph[Bc * LYc * LXc], g_Pl[Bc * LYc * LXc]; // softmax P hi/lo

__device__ __forceinline__ float ex2_fast(float x) {
    float r; asm("ex2.approx.f32 %0, %1;" : "=f"(r) : "f"(x)); return r;
}
__device__ __forceinline__ uint32_t smem_u32(const void* p) {
    uint32_t a;
    asm("{ .reg .u64 t; cvta.to.shared.u64 t, %1; cvt.u32.u64 %0, t; }"
        : "=r"(a) : "l"(p));
    return a;
}
__device__ __forceinline__ uint32_t packbf(float lo, float hi) {
    uint32_t r;
    asm("cvt.rn.bf16x2.f32 %0, %1, %2;" : "=r"(r) : "f"(hi), "f"(lo));
    return r;
}
__device__ __forceinline__ uint32_t packres(uint32_t h, float lo, float hi) {
    float fl = __uint_as_float(h << 16);
    float fh = __uint_as_float(h & 0xffff0000u);
    return packbf(lo - fl, hi - fh);
}
// f16x2 helpers for the score kernel
__device__ __forceinline__ uint32_t pack_f16x2(float lo, float hi) {
    uint32_t r;
    asm("cvt.rn.f16x2.f32 %0, %1, %2;" : "=r"(r) : "f"(hi), "f"(lo));
    return r;
}
__device__ __forceinline__ uint32_t tanh_f16x2(uint32_t x) {
    uint32_t r; asm("tanh.approx.f16x2 %0, %1;" : "=r"(r) : "r"(x)); return r;
}
__device__ __forceinline__ float2 unpack_f16x2(uint32_t p) {
    float lo, hi;
    asm("{ .reg .f16 a, b;\n\t"
        "mov.b32 {a, b}, %2;\n\t"
        "cvt.f32.f16 %0, a;\n\t"
        "cvt.f32.f16 %1, b;\n\t}"
        : "=f"(lo), "=f"(hi) : "r"(p));
    return make_float2(lo, hi);
}
__device__ __forceinline__ void ldm4(uint32_t* r, uint32_t a) {
    asm volatile("ldmatrix.sync.aligned.m8n8.x4.shared.b16 {%0,%1,%2,%3}, [%4];"
                 : "=r"(r[0]), "=r"(r[1]), "=r"(r[2]), "=r"(r[3]) : "r"(a));
}
__device__ __forceinline__ void mma16816(float* c, const uint32_t* a,
                                         uint32_t b0, uint32_t b1) {
    asm volatile(
        "mma.sync.aligned.m16n8k16.row.col.f32.bf16.bf16.f32 "
        "{%0,%1,%2,%3}, {%4,%5,%6,%7}, {%8,%9}, {%0,%1,%2,%3};"
        : "+f"(c[0]), "+f"(c[1]), "+f"(c[2]), "+f"(c[3])
        : "r"(a[0]), "r"(a[1]), "r"(a[2]), "r"(a[3]), "r"(b0), "r"(b1));
}

// ---------------------------------------------------------------------------
// HMMA GEMM on pre-split bf16 hi/lo operands (unchanged from round 13).
// C[64,64] = A[64,K] @ B[64,K]^T, 3-product hi/lo, fp32 accum.
// ---------------------------------------------------------------------------
__device__ void gemm_mma_pre(const ushort* __restrict__ Ah,
                             const ushort* __restrict__ Al, int lda,
                             const ushort* __restrict__ Bh,
                             const ushort* __restrict__ Bl, int ldb,
                             float* __restrict__ C, int ldc, int K)
{
    __shared__ __align__(16) ushort AHs[2][64 * 40], ALs[2][64 * 40];
    __shared__ __align__(16) ushort BHs[2][64 * 40], BLs[2][64 * 40];

    const int tid = threadIdx.x, wid = tid >> 5, lane = tid & 31;
    const int wm = (wid >> 1) * 32, wn = (wid & 1) * 32;
    const int crow = tid >> 1, ckb = (tid & 1) * 16;
    const int cidx = crow * 40 + ckb;

    const ushort* pAh = Ah + crow * lda + ckb;
    const ushort* pAl = Al + crow * lda + ckb;
    const ushort* pBh = Bh + crow * ldb + ckb;
    const ushort* pBl = Bl + crow * ldb + ckb;

    float c[2][4][4];
    #pragma unroll
    for (int i = 0; i < 2; i++)
        #pragma unroll
        for (int j = 0; j < 4; j++)
            #pragma unroll
            for (int q = 0; q < 4; q++) c[i][j][q] = 0.f;

    *(uint4*)&AHs[0][cidx]     = *(const uint4*)pAh;
    *(uint4*)&AHs[0][cidx + 8] = *(const uint4*)(pAh + 8);
    *(uint4*)&ALs[0][cidx]     = *(const uint4*)pAl;
    *(uint4*)&ALs[0][cidx + 8] = *(const uint4*)(pAl + 8);
    *(uint4*)&BHs[0][cidx]     = *(const uint4*)pBh;
    *(uint4*)&BHs[0][cidx + 8] = *(const uint4*)(pBh + 8);
    *(uint4*)&BLs[0][cidx]     = *(const uint4*)pBl;
    *(uint4*)&BLs[0][cidx + 8] = *(const uint4*)(pBl + 8);
    __syncthreads();

    const int nch = K >> 5;
    int buf = 0;
    for (int ch = 0; ch < nch; ch++) {
        uint4 rah0, rah1, ral0, ral1, rbh0, rbh1, rbl0, rbl1;
        if (ch + 1 < nch) {
            const int nk = (ch + 1) * 32;
            rah0 = *(const uint4*)(pAh + nk); rah1 = *(const uint4*)(pAh + nk + 8);
            ral0 = *(const uint4*)(pAl + nk); ral1 = *(const uint4*)(pAl + nk + 8);
            rbh0 = *(const uint4*)(pBh + nk); rbh1 = *(const uint4*)(pBh + nk + 8);
            rbl0 = *(const uint4*)(pBl + nk); rbl1 = *(const uint4*)(pBl + nk + 8);
        }

        #pragma unroll
        for (int ks = 0; ks < 2; ks++) {
            uint32_t aHf[2][4], aLf[2][4], bHf[2][4], bLf[2][4];
            #pragma unroll
            for (int mt = 0; mt < 2; mt++) {
                const int row = wm + mt * 16 + (lane & 15);
                const int kc  = ks * 16 + (lane >> 4) * 8;
                const int off = row * 40 + kc;
                ldm4(aHf[mt], smem_u32(&AHs[buf][off]));
                ldm4(aLf[mt], smem_u32(&ALs[buf][off]));
            }
            #pragma unroll
            for (int g = 0; g < 2; g++) {
                const int row = wn + g * 16 + ((lane >> 4) << 3) + (lane & 7);
                const int kc  = ks * 16 + ((lane >> 3) & 1) * 8;
                const int off = row * 40 + kc;
                ldm4(bHf[g], smem_u32(&BHs[buf][off]));
                ldm4(bLf[g], smem_u32(&BLs[buf][off]));
            }
            #pragma unroll
            for (int mt = 0; mt < 2; mt++)
                #pragma unroll
                for (int g = 0; g < 2; g++)
                    #pragma unroll
                    for (int h = 0; h < 2; h++) {
                        float* cf = c[mt][g * 2 + h];
                        mma16816(cf, aHf[mt], bHf[g][2*h], bHf[g][2*h+1]);
                        mma16816(cf, aLf[mt], bHf[g][2*h], bHf[g][2*h+1]);
                        mma16816(cf, aHf[mt], bLf[g][2*h], bLf[g][2*h+1]);
                    }
        }

        if (ch + 1 < nch) {
            const int nb = buf ^ 1;
            *(uint4*)&AHs[nb][cidx]     = rah0;
            *(uint4*)&AHs[nb][cidx + 8] = rah1;
            *(uint4*)&ALs[nb][cidx]     = ral0;
            *(uint4*)&ALs[nb][cidx + 8] = ral1;
            *(uint4*)&BHs[nb][cidx]     = rbh0;
            *(uint4*)&BHs[nb][cidx + 8] = rbh1;
            *(uint4*)&BLs[nb][cidx]     = rbl0;
            *(uint4*)&BLs[nb][cidx + 8] = rbl1;
            __syncthreads();
            buf = nb;
        }
    }

    #pragma unroll
    for (int mt = 0; mt < 2; mt++) {
        const int r0 = wm + mt * 16 + (lane >> 2);
        #pragma unroll
        for (int nt = 0; nt < 4; nt++) {
            const int cc = wn + nt * 8 + (lane & 3) * 2;
            float* p = C + r0 * ldc + cc;
            *(float2*)p             = make_float2(c[mt][nt][0], c[mt][nt][1]);
            *(float2*)(p + 8 * ldc) = make_float2(c[mt][nt][2], c[mt][nt][3]);
        }
    }
}

// ---------------------------------------------------------------------------
// Kernel A: split x / y / Wm into bf16 hi/lo in global memory (once).
// ---------------------------------------------------------------------------
__global__ __launch_bounds__(256) void conv_split_kernel(
    const float* __restrict__ x, const float* __restrict__ y,
    const float* __restrict__ W)
{
    const int NX4 = Bc * LXc * Fc / 4;
    const int NY4 = Bc * LYc * Fc / 4;
    const int NW4 = Hc * Fc / 4;
    int i4 = blockIdx.x * 256 + threadIdx.x;
    const float* src; ushort* dh; ushort* dl; int o4;
    if (i4 < NX4)            { src = x; dh = g_xh; dl = g_xl; o4 = i4; }
    else if (i4 < NX4 + NY4) { src = y; dh = g_yh; dl = g_yl; o4 = i4 - NX4; }
    else if (i4 < NX4 + NY4 + NW4)
                             { src = W; dh = g_Wh; dl = g_Wl; o4 = i4 - NX4 - NY4; }
    else return;
    float4 v = ((const float4*)src)[o4];
    uint32_t h0 = packbf(v.x, v.y), h1 = packbf(v.z, v.w);
    uint32_t l0 = packres(h0, v.x, v.y), l1 = packres(h1, v.z, v.w);
    ((uint2*)dh)[o4] = make_uint2(h0, h1);
    ((uint2*)dl)[o4] = make_uint2(l0, l1);
}

// ---------------------------------------------------------------------------
// Kernel B: transpose x -> bf16 hi/lo xT[b][f][l]
// ---------------------------------------------------------------------------
__global__ __launch_bounds__(256) void transpose_x_kernel(const float* __restrict__ x)
{
    __shared__ float t[32][33];
    const int b  = blockIdx.z;
    const int f0 = blockIdx.x * 32;
    const int l0 = blockIdx.y * 32;
    const int tx = threadIdx.x & 31;
    const int ty = threadIdx.x >> 5;

    #pragma unroll
    for (int i = ty; i < 32; i += 8)
        t[i][tx] = x[(b * LXc + l0 + i) * Fc + f0 + tx];
    __syncthreads();
    #pragma unroll
    for (int i = ty; i < 32; i += 8) {
        float v = t[tx][i];
        __nv_bfloat16 h = __float2bfloat16(v);
        __nv_bfloat16 l = __float2bfloat16(v - __bfloat162float(h));
        const int idx = (b * Fc + f0 + i) * LXc + l0 + tx;
        g_xTh[idx] = __bfloat16_as_ushort(h);
        g_xTl[idx] = __bfloat16_as_ushort(l);
    }
}

// ---------------------------------------------------------------------------
// Kernel 1: proj.  grid (Hc/64=4, 1536/64=24, 2)
// ---------------------------------------------------------------------------
__global__ __launch_bounds__(128) void proj_mma_kernel()
{
    const ushort* Ah = blockIdx.z ? g_yh : g_xh;
    const ushort* Al = blockIdx.z ? g_yl : g_xl;
    float*        Out = blockIdx.z ? g_Yp : g_Xp;
    gemm_mma_pre(Ah + blockIdx.y * 64 * Fc, Al + blockIdx.y * 64 * Fc, Fc,
                 g_Wh + blockIdx.x * 64 * Fc, g_Wl + blockIdx.x * 64 * Fc, Fc,
                 Out + blockIdx.y * 64 * Hc + blockIdx.x * 64, Hc, Fc);
}

// ---------------------------------------------------------------------------
// Kernel 4: outgemm.  grid (Fc/64=8, LYc/64=6, Bc)
// ---------------------------------------------------------------------------
__global__ __launch_bounds__(128) void outgemm_mma_kernel(float* __restrict__ out)
{
    const int b = blockIdx.z;
    gemm_mma_pre(g_Ph  + (b * LYc + blockIdx.y * 64) * LXc,
                 g_Pl  + (b * LYc + blockIdx.y * 64) * LXc, LXc,
                 g_xTh + (b * Fc + blockIdx.x * 64) * LXc,
                 g_xTl + (b * Fc + blockIdx.x * 64) * LXc, LXc,
                 out + (b * LYc + blockIdx.y * 64) * Fc + blockIdx.x * 64,
                 Fc, LXc);
}

// ---------------------------------------------------------------------------
// Kernel 2 (NEW): tanh-score with f16x2 tanh (halved MUFU) + double-buffered
// smem with register prefetch (hides per-chunk LDG latency).
// S[b,y,l] = sum_h vm[h] * tanh(Xp[b,l,h] - Yp[b,y,h])
// Subtract in f32, pack->f16x2, tanh.approx.f16x2, unpack->f32, FFMA f32.
// ---------------------------------------------------------------------------
__global__ __launch_bounds__(256) void score_tile_kernel(const float* __restrict__ vm)
{
    const int b  = blockIdx.z;
    const int y0 = blockIdx.y * 64;
    const int l0 = blockIdx.x * 64;

    __shared__ float Ys[2][16][68];
    __shared__ float Xs[2][16][68];
    __shared__ float Vs[Hc];

    const int tid = threadIdx.x;
    for (int i = tid; i < Hc; i += 256) Vs[i] = vm[i];

    const int lrow = tid >> 2;
    const int f4   = (tid & 3) * 4;
    const int tx   = tid & 15;
    const int ty   = tid >> 4;

    const float* Yb = g_Yp + (b * LYc + y0) * Hc;
    const float* Xb = g_Xp + (b * LXc + l0) * Hc;

    float acc[4][4] = {};

    // prologue: chunk 0 -> buf 0
    {
        float4 av = *(const float4*)&Yb[lrow * Hc + f4];
        float4 bv = *(const float4*)&Xb[lrow * Hc + f4];
        Ys[0][f4 + 0][lrow] = av.x; Ys[0][f4 + 1][lrow] = av.y;
        Ys[0][f4 + 2][lrow] = av.z; Ys[0][f4 + 3][lrow] = av.w;
        Xs[0][f4 + 0][lrow] = bv.x; Xs[0][f4 + 1][lrow] = bv.y;
        Xs[0][f4 + 2][lrow] = bv.z; Xs[0][f4 + 3][lrow] = bv.w;
    }
    __syncthreads();

    int buf = 0;
    const int nch = Hc / 16;   // 16 chunks
    for (int c = 0; c < nch; c++) {
        float4 av, bv;
        if (c + 1 < nch) {
            const int nk = (c + 1) * 16;
            av = *(const float4*)&Yb[lrow * Hc + nk + f4];
            bv = *(const float4*)&Xb[lrow * Hc + nk + f4];
        }

        #pragma unroll
        for (int kk = 0; kk < 16; kk++) {
            const float v = Vs[c * 16 + kk];
            float4 yv4 = *(const float4*)&Ys[buf][kk][ty * 4];
            float4 xv4 = *(const float4*)&Xs[buf][kk][tx * 4];
            const float ys[4] = {yv4.x, yv4.y, yv4.z, yv4.w};
            #pragma unroll
            for (int i = 0; i < 4; i++) {
                float d0 = xv4.x - ys[i];
                float d1 = xv4.y - ys[i];
                float d2 = xv4.z - ys[i];
                float d3 = xv4.w - ys[i];
                uint32_t pa = pack_f16x2(d0, d1);
                uint32_t pb = pack_f16x2(d2, d3);
                uint32_t ta = tanh_f16x2(pa);
                uint32_t tb = tanh_f16x2(pb);
                float2 fa = unpack_f16x2(ta);
                float2 fb = unpack_f16x2(tb);
                acc[i][0] = fmaf(v, fa.x, acc[i][0]);
                acc[i][1] = fmaf(v, fa.y, acc[i][1]);
                acc[i][2] = fmaf(v, fb.x, acc[i][2]);
                acc[i][3] = fmaf(v, fb.y, acc[i][3]);
            }
        }

        if (c + 1 < nch) {
            const int nb = buf ^ 1;
            Ys[nb][f4 + 0][lrow] = av.x; Ys[nb][f4 + 1][lrow] = av.y;
            Ys[nb][f4 + 2][lrow] = av.z; Ys[nb][f4 + 3][lrow] = av.w;
            Xs[nb][f4 + 0][lrow] = bv.x; Xs[nb][f4 + 1][lrow] = bv.y;
            Xs[nb][f4 + 2][lrow] = bv.z; Xs[nb][f4 + 3][lrow] = bv.w;
            __syncthreads();
            buf = nb;
        }
    }

    float* Sb = g_S + (b * LYc + y0) * LXc + l0;
    #pragma unroll
    for (int i = 0; i < 4; i++) {
        float4 st = make_float4(acc[i][0], acc[i][1], acc[i][2], acc[i][3]);
        *(float4*)&Sb[(ty * 4 + i) * LXc + tx * 4] = st;
    }
}

// ---------------------------------------------------------------------------
// Kernel 3: softmax over l; writes P as bf16 hi/lo directly. Warp per row.
// ---------------------------------------------------------------------------
__global__ __launch_bounds__(256) void softmax_kernel()
{
    const int b    = blockIdx.y;
    const int y    = blockIdx.x * 8 + (threadIdx.x >> 5);
    const int lane = threadIdx.x & 31;

    const float* Srow = g_S + (b * LYc + y) * LXc;
    float v[12];
    float mx = -1e30f;
    #pragma unroll
    for (int j = 0; j < 12; j++) {
        v[j] = Srow[lane + 32 * j];
        mx = fmaxf(mx, v[j]);
    }
    #pragma unroll
    for (int o = 16; o; o >>= 1)
        mx = fmaxf(mx, __shfl_xor_sync(0xffffffffu, mx, o));
    float sum = 0.f;
    #pragma unroll
    for (int j = 0; j < 12; j++) {
        v[j] = ex2_fast((v[j] - mx) * 1.4426950408889634f);
        sum += v[j];
    }
    #pragma unroll
    for (int o = 16; o; o >>= 1)
        sum += __shfl_xor_sync(0xffffffffu, sum, o);
    float inv = 1.0f / sum;

    const int rbase = (b * LYc + y) * LXc;
    #pragma unroll
    for (int j = 0; j < 12; j++) {
        float p = v[j] * inv;
        __nv_bfloat16 h = __float2bfloat16(p);
        __nv_bfloat16 l = __float2bfloat16(p - __bfloat162float(h));
        g_Ph[rbase + lane + 32 * j] = __bfloat16_as_ushort(h);
        g_Pl[rbase + lane + 32 * j] = __bfloat16_as_ushort(l);
    }
}

// ---------------------------------------------------------------------------
extern "C" void kernel_launch(void* const* d_in, const int* in_sizes, int n_in,
                              void* d_out, int out_size)
{
    const float* x  = (const float*)d_in[0];
    const float* y  = (const float*)d_in[1];
    const float* Wm = (const float*)d_in[2];
    const float* vm = (const float*)d_in[3];
    float* out = (float*)d_out;

    const int NTOT4 = (Bc * LXc * Fc + Bc * LYc * Fc + Hc * Fc) / 4;
    conv_split_kernel <<<(NTOT4 + 255) / 256, 256>>>(x, y, Wm);
    transpose_x_kernel<<<dim3(Fc / 32, LXc / 32, Bc), 256>>>(x);
    proj_mma_kernel   <<<dim3(Hc / 64, (LXc * Bc) / 64, 2), 128>>>();
    score_tile_kernel <<<dim3(LXc / 64, LYc / 64, Bc), 256>>>(vm);
    softmax_kernel    <<<dim3(LYc / 8, Bc), 256>>>();
    outgemm_mma_kernel<<<dim3(Fc / 64, LYc / 64, Bc), 128>>>(out);
}

// round 15
// speedup vs baseline: 1.0750x; 1.0283x over previous
#include <cuda_runtime.h>
#include <cuda_bf16.h>
#include <cstdint>

#define Bc  4
#define LXc 384
#define LYc 384
#define Hc  256
#define Fc  512

// scratch (allocation-free rule: __device__ globals)
__device__ float  g_Xp[Bc * LXc * Hc];     // x @ Wm^T (fp32, for score)
__device__ float  g_Yp[Bc * LYc * Hc];     // y @ Wm^T
__device__ float  g_S [Bc * LYc * LXc];    // partial scores, h in [0,128)
__device__ float  g_S2[Bc * LYc * LXc];    // partial scores, h in [128,256)
__device__ ushort g_xh[Bc * LXc * Fc], g_xl[Bc * LXc * Fc];   // x  hi/lo bf16
__device__ ushort g_yh[Bc * LYc * Fc], g_yl[Bc * LYc * Fc];   // y  hi/lo
__device__ ushort g_Wh[Hc * Fc],       g_Wl[Hc * Fc];         // Wm hi/lo
__device__ ushort g_xTh[Bc * Fc * LXc], g_xTl[Bc * Fc * LXc]; // xT hi/lo
__device__ ushort g_Ph[Bc * LYc * LXc], g_Pl[Bc * LYc * LXc]; // softmax P hi/lo

__device__ __forceinline__ float ex2_fast(float x) {
    float r; asm("ex2.approx.f32 %0, %1;" : "=f"(r) : "f"(x)); return r;
}
__device__ __forceinline__ uint32_t smem_u32(const void* p) {
    uint32_t a;
    asm("{ .reg .u64 t; cvta.to.shared.u64 t, %1; cvt.u32.u64 %0, t; }"
        : "=r"(a) : "l"(p));
    return a;
}
__device__ __forceinline__ uint32_t packbf(float lo, float hi) {
    uint32_t r;
    asm("cvt.rn.bf16x2.f32 %0, %1, %2;" : "=r"(r) : "f"(hi), "f"(lo));
    return r;
}
__device__ __forceinline__ uint32_t packres(uint32_t h, float lo, float hi) {
    float fl = __uint_as_float(h << 16);
    float fh = __uint_as_float(h & 0xffff0000u);
    return packbf(lo - fl, hi - fh);
}
// f16x2 helpers for the score kernel
__device__ __forceinline__ uint32_t pack_f16x2(float lo, float hi) {
    uint32_t r;
    asm("cvt.rn.f16x2.f32 %0, %1, %2;" : "=r"(r) : "f"(hi), "f"(lo));
    return r;
}
__device__ __forceinline__ uint32_t tanh_f16x2(uint32_t x) {
    uint32_t r; asm("tanh.approx.f16x2 %0, %1;" : "=r"(r) : "r"(x)); return r;
}
__device__ __forceinline__ float2 unpack_f16x2(uint32_t p) {
    float lo, hi;
    asm("{ .reg .f16 a, b;\n\t"
        "mov.b32 {a, b}, %2;\n\t"
        "cvt.f32.f16 %0, a;\n\t"
        "cvt.f32.f16 %1, b;\n\t}"
        : "=f"(lo), "=f"(hi) : "r"(p));
    return make_float2(lo, hi);
}
__device__ __forceinline__ void ldm4(uint32_t* r, uint32_t a) {
    asm volatile("ldmatrix.sync.aligned.m8n8.x4.shared.b16 {%0,%1,%2,%3}, [%4];"
                 : "=r"(r[0]), "=r"(r[1]), "=r"(r[2]), "=r"(r[3]) : "r"(a));
}
__device__ __forceinline__ void mma16816(float* c, const uint32_t* a,
                                         uint32_t b0, uint32_t b1) {
    asm volatile(
        "mma.sync.aligned.m16n8k16.row.col.f32.bf16.bf16.f32 "
        "{%0,%1,%2,%3}, {%4,%5,%6,%7}, {%8,%9}, {%0,%1,%2,%3};"
        : "+f"(c[0]), "+f"(c[1]), "+f"(c[2]), "+f"(c[3])
        : "r"(a[0]), "r"(a[1]), "r"(a[2]), "r"(a[3]), "r"(b0), "r"(b1));
}

// ---------------------------------------------------------------------------
// HMMA GEMM on pre-split bf16 hi/lo operands (unchanged — validated R12-14).
// C[64,64] = A[64,K] @ B[64,K]^T, 3-product hi/lo, fp32 accum.
// ---------------------------------------------------------------------------
__device__ void gemm_mma_pre(const ushort* __restrict__ Ah,
                             const ushort* __restrict__ Al, int lda,
                             const ushort* __restrict__ Bh,
                             const ushort* __restrict__ Bl, int ldb,
                             float* __restrict__ C, int ldc, int K)
{
    __shared__ __align__(16) ushort AHs[2][64 * 40], ALs[2][64 * 40];
    __shared__ __align__(16) ushort BHs[2][64 * 40], BLs[2][64 * 40];

    const int tid = threadIdx.x, wid = tid >> 5, lane = tid & 31;
    const int wm = (wid >> 1) * 32, wn = (wid & 1) * 32;
    const int crow = tid >> 1, ckb = (tid & 1) * 16;
    const int cidx = crow * 40 + ckb;

    const ushort* pAh = Ah + crow * lda + ckb;
    const ushort* pAl = Al + crow * lda + ckb;
    const ushort* pBh = Bh + crow * ldb + ckb;
    const ushort* pBl = Bl + crow * ldb + ckb;

    float c[2][4][4];
    #pragma unroll
    for (int i = 0; i < 2; i++)
        #pragma unroll
        for (int j = 0; j < 4; j++)
            #pragma unroll
            for (int q = 0; q < 4; q++) c[i][j][q] = 0.f;

    *(uint4*)&AHs[0][cidx]     = *(const uint4*)pAh;
    *(uint4*)&AHs[0][cidx + 8] = *(const uint4*)(pAh + 8);
    *(uint4*)&ALs[0][cidx]     = *(const uint4*)pAl;
    *(uint4*)&ALs[0][cidx + 8] = *(const uint4*)(pAl + 8);
    *(uint4*)&BHs[0][cidx]     = *(const uint4*)pBh;
    *(uint4*)&BHs[0][cidx + 8] = *(const uint4*)(pBh + 8);
    *(uint4*)&BLs[0][cidx]     = *(const uint4*)pBl;
    *(uint4*)&BLs[0][cidx + 8] = *(const uint4*)(pBl + 8);
    __syncthreads();

    const int nch = K >> 5;
    int buf = 0;
    for (int ch = 0; ch < nch; ch++) {
        uint4 rah0, rah1, ral0, ral1, rbh0, rbh1, rbl0, rbl1;
        if (ch + 1 < nch) {
            const int nk = (ch + 1) * 32;
            rah0 = *(const uint4*)(pAh + nk); rah1 = *(const uint4*)(pAh + nk + 8);
            ral0 = *(const uint4*)(pAl + nk); ral1 = *(const uint4*)(pAl + nk + 8);
            rbh0 = *(const uint4*)(pBh + nk); rbh1 = *(const uint4*)(pBh + nk + 8);
            rbl0 = *(const uint4*)(pBl + nk); rbl1 = *(const uint4*)(pBl + nk + 8);
        }

        #pragma unroll
        for (int ks = 0; ks < 2; ks++) {
            uint32_t aHf[2][4], aLf[2][4], bHf[2][4], bLf[2][4];
            #pragma unroll
            for (int mt = 0; mt < 2; mt++) {
                const int row = wm + mt * 16 + (lane & 15);
                const int kc  = ks * 16 + (lane >> 4) * 8;
                const int off = row * 40 + kc;
                ldm4(aHf[mt], smem_u32(&AHs[buf][off]));
                ldm4(aLf[mt], smem_u32(&ALs[buf][off]));
            }
            #pragma unroll
            for (int g = 0; g < 2; g++) {
                const int row = wn + g * 16 + ((lane >> 4) << 3) + (lane & 7);
                const int kc  = ks * 16 + ((lane >> 3) & 1) * 8;
                const int off = row * 40 + kc;
                ldm4(bHf[g], smem_u32(&BHs[buf][off]));
                ldm4(bLf[g], smem_u32(&BLs[buf][off]));
            }
            #pragma unroll
            for (int mt = 0; mt < 2; mt++)
                #pragma unroll
                for (int g = 0; g < 2; g++)
                    #pragma unroll
                    for (int h = 0; h < 2; h++) {
                        float* cf = c[mt][g * 2 + h];
                        mma16816(cf, aHf[mt], bHf[g][2*h], bHf[g][2*h+1]);
                        mma16816(cf, aLf[mt], bHf[g][2*h], bHf[g][2*h+1]);
                        mma16816(cf, aHf[mt], bLf[g][2*h], bLf[g][2*h+1]);
                    }
        }

        if (ch + 1 < nch) {
            const int nb = buf ^ 1;
            *(uint4*)&AHs[nb][cidx]     = rah0;
            *(uint4*)&AHs[nb][cidx + 8] = rah1;
            *(uint4*)&ALs[nb][cidx]     = ral0;
            *(uint4*)&ALs[nb][cidx + 8] = ral1;
            *(uint4*)&BHs[nb][cidx]     = rbh0;
            *(uint4*)&BHs[nb][cidx + 8] = rbh1;
            *(uint4*)&BLs[nb][cidx]     = rbl0;
            *(uint4*)&BLs[nb][cidx + 8] = rbl1;
            __syncthreads();
            buf = nb;
        }
    }

    #pragma unroll
    for (int mt = 0; mt < 2; mt++) {
        const int r0 = wm + mt * 16 + (lane >> 2);
        #pragma unroll
        for (int nt = 0; nt < 4; nt++) {
            const int cc = wn + nt * 8 + (lane & 3) * 2;
            float* p = C + r0 * ldc + cc;
            *(float2*)p             = make_float2(c[mt][nt][0], c[mt][nt][1]);
            *(float2*)(p + 8 * ldc) = make_float2(c[mt][nt][2], c[mt][nt][3]);
        }
    }
}

// ---------------------------------------------------------------------------
// Kernel A: split x / y / Wm into bf16 hi/lo in global memory (once).
// ---------------------------------------------------------------------------
__global__ __launch_bounds__(256) void conv_split_kernel(
    const float* __restrict__ x, const float* __restrict__ y,
    const float* __restrict__ W)
{
    const int NX4 = Bc * LXc * Fc / 4;
    const int NY4 = Bc * LYc * Fc / 4;
    const int NW4 = Hc * Fc / 4;
    int i4 = blockIdx.x * 256 + threadIdx.x;
    const float* src; ushort* dh; ushort* dl; int o4;
    if (i4 < NX4)            { src = x; dh = g_xh; dl = g_xl; o4 = i4; }
    else if (i4 < NX4 + NY4) { src = y; dh = g_yh; dl = g_yl; o4 = i4 - NX4; }
    else if (i4 < NX4 + NY4 + NW4)
                             { src = W; dh = g_Wh; dl = g_Wl; o4 = i4 - NX4 - NY4; }
    else return;
    float4 v = ((const float4*)src)[o4];
    uint32_t h0 = packbf(v.x, v.y), h1 = packbf(v.z, v.w);
    uint32_t l0 = packres(h0, v.x, v.y), l1 = packres(h1, v.z, v.w);
    ((uint2*)dh)[o4] = make_uint2(h0, h1);
    ((uint2*)dl)[o4] = make_uint2(l0, l1);
}

// ---------------------------------------------------------------------------
// Kernel B: transpose x -> bf16 hi/lo xT[b][f][l]
// ---------------------------------------------------------------------------
__global__ __launch_bounds__(256) void transpose_x_kernel(const float* __restrict__ x)
{
    __shared__ float t[32][33];
    const int b  = blockIdx.z;
    const int f0 = blockIdx.x * 32;
    const int l0 = blockIdx.y * 32;
    const int tx = threadIdx.x & 31;
    const int ty = threadIdx.x >> 5;

    #pragma unroll
    for (int i = ty; i < 32; i += 8)
        t[i][tx] = x[(b * LXc + l0 + i) * Fc + f0 + tx];
    __syncthreads();
    #pragma unroll
    for (int i = ty; i < 32; i += 8) {
        float v = t[tx][i];
        __nv_bfloat16 h = __float2bfloat16(v);
        __nv_bfloat16 l = __float2bfloat16(v - __bfloat162float(h));
        const int idx = (b * Fc + f0 + i) * LXc + l0 + tx;
        g_xTh[idx] = __bfloat16_as_ushort(h);
        g_xTl[idx] = __bfloat16_as_ushort(l);
    }
}

// ---------------------------------------------------------------------------
// Kernel 1: proj.  grid (Hc/64=4, 1536/64=24, 2)
// ---------------------------------------------------------------------------
__global__ __launch_bounds__(128) void proj_mma_kernel()
{
    const ushort* Ah = blockIdx.z ? g_yh : g_xh;
    const ushort* Al = blockIdx.z ? g_yl : g_xl;
    float*        Out = blockIdx.z ? g_Yp : g_Xp;
    gemm_mma_pre(Ah + blockIdx.y * 64 * Fc, Al + blockIdx.y * 64 * Fc, Fc,
                 g_Wh + blockIdx.x * 64 * Fc, g_Wl + blockIdx.x * 64 * Fc, Fc,
                 Out + blockIdx.y * 64 * Hc + blockIdx.x * 64, Hc, Fc);
}

// ---------------------------------------------------------------------------
// Kernel 4: outgemm.  grid (Fc/64=8, LYc/64=6, Bc)
// ---------------------------------------------------------------------------
__global__ __launch_bounds__(128) void outgemm_mma_kernel(float* __restrict__ out)
{
    const int b = blockIdx.z;
    gemm_mma_pre(g_Ph  + (b * LYc + blockIdx.y * 64) * LXc,
                 g_Pl  + (b * LYc + blockIdx.y * 64) * LXc, LXc,
                 g_xTh + (b * Fc + blockIdx.x * 64) * LXc,
                 g_xTl + (b * Fc + blockIdx.x * 64) * LXc, LXc,
                 out + (b * LYc + blockIdx.y * 64) * Fc + blockIdx.x * 64,
                 Fc, LXc);
}

// ---------------------------------------------------------------------------
// Kernel 2: tanh-score, SPLIT-K over h (two halves of 128).
// grid (LXc/64, LYc/64, Bc*2): z = b*2 + half.  half 0 -> g_S, half 1 -> g_S2.
// 288 blocks -> 2 blocks/SM -> 4 warps/SMSP (latency cover).
// f16x2 tanh path identical to validated round 14.
// ---------------------------------------------------------------------------
__global__ __launch_bounds__(256) void score_tile_kernel(const float* __restrict__ vm)
{
    const int b    = blockIdx.z >> 1;
    const int half = blockIdx.z & 1;
    const int kb   = half * 128;           // h base for this block
    const int y0   = blockIdx.y * 64;
    const int l0   = blockIdx.x * 64;

    __shared__ float Ys[2][16][68];
    __shared__ float Xs[2][16][68];
    __shared__ float Vs[128];

    const int tid = threadIdx.x;
    if (tid < 128) Vs[tid] = vm[kb + tid];

    const int lrow = tid >> 2;
    const int f4   = (tid & 3) * 4;
    const int tx   = tid & 15;
    const int ty   = tid >> 4;

    const float* Yb = g_Yp + (b * LYc + y0) * Hc + kb;
    const float* Xb = g_Xp + (b * LXc + l0) * Hc + kb;

    float acc[4][4] = {};

    // prologue: chunk 0 -> buf 0
    {
        float4 av = *(const float4*)&Yb[lrow * Hc + f4];
        float4 bv = *(const float4*)&Xb[lrow * Hc + f4];
        Ys[0][f4 + 0][lrow] = av.x; Ys[0][f4 + 1][lrow] = av.y;
        Ys[0][f4 + 2][lrow] = av.z; Ys[0][f4 + 3][lrow] = av.w;
        Xs[0][f4 + 0][lrow] = bv.x; Xs[0][f4 + 1][lrow] = bv.y;
        Xs[0][f4 + 2][lrow] = bv.z; Xs[0][f4 + 3][lrow] = bv.w;
    }
    __syncthreads();

    int buf = 0;
    const int nch = 128 / 16;   // 8 chunks
    for (int c = 0; c < nch; c++) {
        float4 av, bv;
        if (c + 1 < nch) {
            const int nk = (c + 1) * 16;
            av = *(const float4*)&Yb[lrow * Hc + nk + f4];
            bv = *(const float4*)&Xb[lrow * Hc + nk + f4];
        }

        #pragma unroll
        for (int kk = 0; kk < 16; kk++) {
            const float v = Vs[c * 16 + kk];
            float4 yv4 = *(const float4*)&Ys[buf][kk][ty * 4];
            float4 xv4 = *(const float4*)&Xs[buf][kk][tx * 4];
            const float ys[4] = {yv4.x, yv4.y, yv4.z, yv4.w};
            #pragma unroll
            for (int i = 0; i < 4; i++) {
                float d0 = xv4.x - ys[i];
                float d1 = xv4.y - ys[i];
                float d2 = xv4.z - ys[i];
                float d3 = xv4.w - ys[i];
                uint32_t pa = pack_f16x2(d0, d1);
                uint32_t pb = pack_f16x2(d2, d3);
                uint32_t ta = tanh_f16x2(pa);
                uint32_t tb = tanh_f16x2(pb);
                float2 fa = unpack_f16x2(ta);
                float2 fb = unpack_f16x2(tb);
                acc[i][0] = fmaf(v, fa.x, acc[i][0]);
                acc[i][1] = fmaf(v, fa.y, acc[i][1]);
                acc[i][2] = fmaf(v, fb.x, acc[i][2]);
                acc[i][3] = fmaf(v, fb.y, acc[i][3]);
            }
        }

        if (c + 1 < nch) {
            const int nb = buf ^ 1;
            Ys[nb][f4 + 0][lrow] = av.x; Ys[nb][f4 + 1][lrow] = av.y;
            Ys[nb][f4 + 2][lrow] = av.z; Ys[nb][f4 + 3][lrow] = av.w;
            Xs[nb][f4 + 0][lrow] = bv.x; Xs[nb][f4 + 1][lrow] = bv.y;
            Xs[nb][f4 + 2][lrow] = bv.z; Xs[nb][f4 + 3][lrow] = bv.w;
            __syncthreads();
            buf = nb;
        }
    }

    float* Sb = (half ? g_S2 : g_S) + (b * LYc + y0) * LXc + l0;
    #pragma unroll
    for (int i = 0; i < 4; i++) {
        float4 st = make_float4(acc[i][0], acc[i][1], acc[i][2], acc[i][3]);
        *(float4*)&Sb[(ty * 4 + i) * LXc + tx * 4] = st;
    }
}

// ---------------------------------------------------------------------------
// Kernel 3: softmax over l (sums the two split-K partials);
// writes P as bf16 hi/lo directly. Warp per row.
// ---------------------------------------------------------------------------
__global__ __launch_bounds__(256) void softmax_kernel()
{
    const int b    = blockIdx.y;
    const int y    = blockIdx.x * 8 + (threadIdx.x >> 5);
    const int lane = threadIdx.x & 31;

    const int rbase = (b * LYc + y) * LXc;
    float v[12];
    float mx = -1e30f;
    #pragma unroll
    for (int j = 0; j < 12; j++) {
        const int idx = rbase + lane + 32 * j;
        v[j] = g_S[idx] + g_S2[idx];
        mx = fmaxf(mx, v[j]);
    }
    #pragma unroll
    for (int o = 16; o; o >>= 1)
        mx = fmaxf(mx, __shfl_xor_sync(0xffffffffu, mx, o));
    float sum = 0.f;
    #pragma unroll
    for (int j = 0; j < 12; j++) {
        v[j] = ex2_fast((v[j] - mx) * 1.4426950408889634f);
        sum += v[j];
    }
    #pragma unroll
    for (int o = 16; o; o >>= 1)
        sum += __shfl_xor_sync(0xffffffffu, sum, o);
    float inv = 1.0f / sum;

    #pragma unroll
    for (int j = 0; j < 12; j++) {
        float p = v[j] * inv;
        __nv_bfloat16 h = __float2bfloat16(p);
        __nv_bfloat16 l = __float2bfloat16(p - __bfloat162float(h));
        g_Ph[rbase + lane + 32 * j] = __bfloat16_as_ushort(h);
        g_Pl[rbase + lane + 32 * j] = __bfloat16_as_ushort(l);
    }
}

// ---------------------------------------------------------------------------
extern "C" void kernel_launch(void* const* d_in, const int* in_sizes, int n_in,
                              void* d_out, int out_size)
{
    const float* x  = (const float*)d_in[0];
    const float* y  = (const float*)d_in[1];
    const float* Wm = (const float*)d_in[2];
    const float* vm = (const float*)d_in[3];
    float* out = (float*)d_out;

    const int NTOT4 = (Bc * LXc * Fc + Bc * LYc * Fc + Hc * Fc) / 4;
    conv_split_kernel <<<(NTOT4 + 255) / 256, 256>>>(x, y, Wm);
    transpose_x_kernel<<<dim3(Fc / 32, LXc / 32, Bc), 256>>>(x);
    proj_mma_kernel   <<<dim3(Hc / 64, (LXc * Bc) / 64, 2), 128>>>();
    score_tile_kernel <<<dim3(LXc / 64, LYc / 64, Bc * 2), 256>>>(vm);
    softmax_kernel    <<<dim3(LYc / 8, Bc), 256>>>();
    outgemm_mma_kernel<<<dim3(Fc / 64, LYc / 64, Bc), 128>>>(out);
}

// round 16
// speedup vs baseline: 1.1019x; 1.0251x over previous
#include <cuda_runtime.h>
#include <cuda_bf16.h>
#include <cstdint>

#define Bc  4
#define LXc 384
#define LYc 384
#define Hc  256
#define Fc  512

// scratch (allocation-free rule: __device__ globals)
__device__ float  g_Xp[Bc * LXc * Hc];     // x @ Wm^T (fp32, for score)
__device__ float  g_Yp[Bc * LYc * Hc];     // y @ Wm^T
__device__ float  g_S [Bc * LYc * LXc];    // partial scores, h in [0,128)
__device__ float  g_S2[Bc * LYc * LXc];    // partial scores, h in [128,256)
__device__ ushort g_xh[Bc * LXc * Fc], g_xl[Bc * LXc * Fc];   // x  hi/lo bf16
__device__ ushort g_yh[Bc * LYc * Fc], g_yl[Bc * LYc * Fc];   // y  hi/lo
__device__ ushort g_Wh[Hc * Fc],       g_Wl[Hc * Fc];         // Wm hi/lo
__device__ ushort g_xTh[Bc * Fc * LXc], g_xTl[Bc * Fc * LXc]; // xT hi/lo
__device__ ushort g_Ph[Bc * LYc * LXc], g_Pl[Bc * LYc * LXc]; // softmax P hi/lo

__device__ __forceinline__ float ex2_fast(float x) {
    float r; asm("ex2.approx.f32 %0, %1;" : "=f"(r) : "f"(x)); return r;
}
__device__ __forceinline__ uint32_t smem_u32(const void* p) {
    uint32_t a;
    asm("{ .reg .u64 t; cvta.to.shared.u64 t, %1; cvt.u32.u64 %0, t; }"
        : "=r"(a) : "l"(p));
    return a;
}
__device__ __forceinline__ uint32_t packbf(float lo, float hi) {
    uint32_t r;
    asm("cvt.rn.bf16x2.f32 %0, %1, %2;" : "=r"(r) : "f"(hi), "f"(lo));
    return r;
}
__device__ __forceinline__ uint32_t packres(uint32_t h, float lo, float hi) {
    float fl = __uint_as_float(h << 16);
    float fh = __uint_as_float(h & 0xffff0000u);
    return packbf(lo - fl, hi - fh);
}
// f16x2 helpers for the score kernel
__device__ __forceinline__ uint32_t pack_f16x2(float lo, float hi) {
    uint32_t r;
    asm("cvt.rn.f16x2.f32 %0, %1, %2;" : "=r"(r) : "f"(hi), "f"(lo));
    return r;
}
__device__ __forceinline__ uint32_t hsub2(uint32_t a, uint32_t b) {
    uint32_t r; asm("sub.f16x2 %0, %1, %2;" : "=r"(r) : "r"(a), "r"(b));
    return r;
}
__device__ __forceinline__ uint32_t tanh_f16x2(uint32_t x) {
    uint32_t r; asm("tanh.approx.f16x2 %0, %1;" : "=r"(r) : "r"(x)); return r;
}
__device__ __forceinline__ float2 unpack_f16x2(uint32_t p) {
    float lo, hi;
    asm("{ .reg .f16 a, b;\n\t"
        "mov.b32 {a, b}, %2;\n\t"
        "cvt.f32.f16 %0, a;\n\t"
        "cvt.f32.f16 %1, b;\n\t}"
        : "=f"(lo), "=f"(hi) : "r"(p));
    return make_float2(lo, hi);
}
__device__ __forceinline__ void ldm4(uint32_t* r, uint32_t a) {
    asm volatile("ldmatrix.sync.aligned.m8n8.x4.shared.b16 {%0,%1,%2,%3}, [%4];"
                 : "=r"(r[0]), "=r"(r[1]), "=r"(r[2]), "=r"(r[3]) : "r"(a));
}
__device__ __forceinline__ void mma16816(float* c, const uint32_t* a,
                                         uint32_t b0, uint32_t b1) {
    asm volatile(
        "mma.sync.aligned.m16n8k16.row.col.f32.bf16.bf16.f32 "
        "{%0,%1,%2,%3}, {%4,%5,%6,%7}, {%8,%9}, {%0,%1,%2,%3};"
        : "+f"(c[0]), "+f"(c[1]), "+f"(c[2]), "+f"(c[3])
        : "r"(a[0]), "r"(a[1]), "r"(a[2]), "r"(a[3]), "r"(b0), "r"(b1));
}

// ---------------------------------------------------------------------------
// HMMA GEMM on pre-split bf16 hi/lo operands (unchanged — validated R12-15).
// ---------------------------------------------------------------------------
__device__ void gemm_mma_pre(const ushort* __restrict__ Ah,
                             const ushort* __restrict__ Al, int lda,
                             const ushort* __restrict__ Bh,
                             const ushort* __restrict__ Bl, int ldb,
                             float* __restrict__ C, int ldc, int K)
{
    __shared__ __align__(16) ushort AHs[2][64 * 40], ALs[2][64 * 40];
    __shared__ __align__(16) ushort BHs[2][64 * 40], BLs[2][64 * 40];

    const int tid = threadIdx.x, wid = tid >> 5, lane = tid & 31;
    const int wm = (wid >> 1) * 32, wn = (wid & 1) * 32;
    const int crow = tid >> 1, ckb = (tid & 1) * 16;
    const int cidx = crow * 40 + ckb;

    const ushort* pAh = Ah + crow * lda + ckb;
    const ushort* pAl = Al + crow * lda + ckb;
    const ushort* pBh = Bh + crow * ldb + ckb;
    const ushort* pBl = Bl + crow * ldb + ckb;

    float c[2][4][4];
    #pragma unroll
    for (int i = 0; i < 2; i++)
        #pragma unroll
        for (int j = 0; j < 4; j++)
            #pragma unroll
            for (int q = 0; q < 4; q++) c[i][j][q] = 0.f;

    *(uint4*)&AHs[0][cidx]     = *(const uint4*)pAh;
    *(uint4*)&AHs[0][cidx + 8] = *(const uint4*)(pAh + 8);
    *(uint4*)&ALs[0][cidx]     = *(const uint4*)pAl;
    *(uint4*)&ALs[0][cidx + 8] = *(const uint4*)(pAl + 8);
    *(uint4*)&BHs[0][cidx]     = *(const uint4*)pBh;
    *(uint4*)&BHs[0][cidx + 8] = *(const uint4*)(pBh + 8);
    *(uint4*)&BLs[0][cidx]     = *(const uint4*)pBl;
    *(uint4*)&BLs[0][cidx + 8] = *(const uint4*)(pBl + 8);
    __syncthreads();

    const int nch = K >> 5;
    int buf = 0;
    for (int ch = 0; ch < nch; ch++) {
        uint4 rah0, rah1, ral0, ral1, rbh0, rbh1, rbl0, rbl1;
        if (ch + 1 < nch) {
            const int nk = (ch + 1) * 32;
            rah0 = *(const uint4*)(pAh + nk); rah1 = *(const uint4*)(pAh + nk + 8);
            ral0 = *(const uint4*)(pAl + nk); ral1 = *(const uint4*)(pAl + nk + 8);
            rbh0 = *(const uint4*)(pBh + nk); rbh1 = *(const uint4*)(pBh + nk + 8);
            rbl0 = *(const uint4*)(pBl + nk); rbl1 = *(const uint4*)(pBl + nk + 8);
        }

        #pragma unroll
        for (int ks = 0; ks < 2; ks++) {
            uint32_t aHf[2][4], aLf[2][4], bHf[2][4], bLf[2][4];
            #pragma unroll
            for (int mt = 0; mt < 2; mt++) {
                const int row = wm + mt * 16 + (lane & 15);
                const int kc  = ks * 16 + (lane >> 4) * 8;
                const int off = row * 40 + kc;
                ldm4(aHf[mt], smem_u32(&AHs[buf][off]));
                ldm4(aLf[mt], smem_u32(&ALs[buf][off]));
            }
            #pragma unroll
            for (int g = 0; g < 2; g++) {
                const int row = wn + g * 16 + ((lane >> 4) << 3) + (lane & 7);
                const int kc  = ks * 16 + ((lane >> 3) & 1) * 8;
                const int off = row * 40 + kc;
                ldm4(bHf[g], smem_u32(&BHs[buf][off]));
                ldm4(bLf[g], smem_u32(&BLs[buf][off]));
            }
            #pragma unroll
            for (int mt = 0; mt < 2; mt++)
                #pragma unroll
                for (int g = 0; g < 2; g++)
                    #pragma unroll
                    for (int h = 0; h < 2; h++) {
                        float* cf = c[mt][g * 2 + h];
                        mma16816(cf, aHf[mt], bHf[g][2*h], bHf[g][2*h+1]);
                        mma16816(cf, aLf[mt], bHf[g][2*h], bHf[g][2*h+1]);
                        mma16816(cf, aHf[mt], bLf[g][2*h], bLf[g][2*h+1]);
                    }
        }

        if (ch + 1 < nch) {
            const int nb = buf ^ 1;
            *(uint4*)&AHs[nb][cidx]     = rah0;
            *(uint4*)&AHs[nb][cidx + 8] = rah1;
            *(uint4*)&ALs[nb][cidx]     = ral0;
            *(uint4*)&ALs[nb][cidx + 8] = ral1;
            *(uint4*)&BHs[nb][cidx]     = rbh0;
            *(uint4*)&BHs[nb][cidx + 8] = rbh1;
            *(uint4*)&BLs[nb][cidx]     = rbl0;
            *(uint4*)&BLs[nb][cidx + 8] = rbl1;
            __syncthreads();
            buf = nb;
        }
    }

    #pragma unroll
    for (int mt = 0; mt < 2; mt++) {
        const int r0 = wm + mt * 16 + (lane >> 2);
        #pragma unroll
        for (int nt = 0; nt < 4; nt++) {
            const int cc = wn + nt * 8 + (lane & 3) * 2;
            float* p = C + r0 * ldc + cc;
            *(float2*)p             = make_float2(c[mt][nt][0], c[mt][nt][1]);
            *(float2*)(p + 8 * ldc) = make_float2(c[mt][nt][2], c[mt][nt][3]);
        }
    }
}

// ---------------------------------------------------------------------------
// Kernel A: split x / y / Wm into bf16 hi/lo in global memory (once).
// ---------------------------------------------------------------------------
__global__ __launch_bounds__(256) void conv_split_kernel(
    const float* __restrict__ x, const float* __restrict__ y,
    const float* __restrict__ W)
{
    const int NX4 = Bc * LXc * Fc / 4;
    const int NY4 = Bc * LYc * Fc / 4;
    const int NW4 = Hc * Fc / 4;
    int i4 = blockIdx.x * 256 + threadIdx.x;
    const float* src; ushort* dh; ushort* dl; int o4;
    if (i4 < NX4)            { src = x; dh = g_xh; dl = g_xl; o4 = i4; }
    else if (i4 < NX4 + NY4) { src = y; dh = g_yh; dl = g_yl; o4 = i4 - NX4; }
    else if (i4 < NX4 + NY4 + NW4)
                             { src = W; dh = g_Wh; dl = g_Wl; o4 = i4 - NX4 - NY4; }
    else return;
    float4 v = ((const float4*)src)[o4];
    uint32_t h0 = packbf(v.x, v.y), h1 = packbf(v.z, v.w);
    uint32_t l0 = packres(h0, v.x, v.y), l1 = packres(h1, v.z, v.w);
    ((uint2*)dh)[o4] = make_uint2(h0, h1);
    ((uint2*)dl)[o4] = make_uint2(l0, l1);
}

// ---------------------------------------------------------------------------
// Kernel B: transpose x -> bf16 hi/lo xT[b][f][l]
// ---------------------------------------------------------------------------
__global__ __launch_bounds__(256) void transpose_x_kernel(const float* __restrict__ x)
{
    __shared__ float t[32][33];
    const int b  = blockIdx.z;
    const int f0 = blockIdx.x * 32;
    const int l0 = blockIdx.y * 32;
    const int tx = threadIdx.x & 31;
    const int ty = threadIdx.x >> 5;

    #pragma unroll
    for (int i = ty; i < 32; i += 8)
        t[i][tx] = x[(b * LXc + l0 + i) * Fc + f0 + tx];
    __syncthreads();
    #pragma unroll
    for (int i = ty; i < 32; i += 8) {
        float v = t[tx][i];
        __nv_bfloat16 h = __float2bfloat16(v);
        __nv_bfloat16 l = __float2bfloat16(v - __bfloat162float(h));
        const int idx = (b * Fc + f0 + i) * LXc + l0 + tx;
        g_xTh[idx] = __bfloat16_as_ushort(h);
        g_xTl[idx] = __bfloat16_as_ushort(l);
    }
}

// ---------------------------------------------------------------------------
// Kernel 1: proj.  grid (Hc/64=4, 1536/64=24, 2)
// ---------------------------------------------------------------------------
__global__ __launch_bounds__(128) void proj_mma_kernel()
{
    const ushort* Ah = blockIdx.z ? g_yh : g_xh;
    const ushort* Al = blockIdx.z ? g_yl : g_xl;
    float*        Out = blockIdx.z ? g_Yp : g_Xp;
    gemm_mma_pre(Ah + blockIdx.y * 64 * Fc, Al + blockIdx.y * 64 * Fc, Fc,
                 g_Wh + blockIdx.x * 64 * Fc, g_Wl + blockIdx.x * 64 * Fc, Fc,
                 Out + blockIdx.y * 64 * Hc + blockIdx.x * 64, Hc, Fc);
}

// ---------------------------------------------------------------------------
// Kernel 4: outgemm.  grid (Fc/64=8, LYc/64=6, Bc)
// ---------------------------------------------------------------------------
__global__ __launch_bounds__(128) void outgemm_mma_kernel(float* __restrict__ out)
{
    const int b = blockIdx.z;
    gemm_mma_pre(g_Ph  + (b * LYc + blockIdx.y * 64) * LXc,
                 g_Pl  + (b * LYc + blockIdx.y * 64) * LXc, LXc,
                 g_xTh + (b * Fc + blockIdx.x * 64) * LXc,
                 g_xTl + (b * Fc + blockIdx.x * 64) * LXc, LXc,
                 out + (b * LYc + blockIdx.y * 64) * Fc + blockIdx.x * 64,
                 Fc, LXc);
}

// ---------------------------------------------------------------------------
// Kernel 2 (NEW): tanh-score, split-K over h, f16x2 front half.
// k-paired f16x2 smem: each u32 = (val[k0], val[k1]) for one row — threads
// pack their OWN float4 at fill time (4 pack cvts per chunk, hoisted out of
// the inner loop). Inner loop per k-pair: 16 HSUB2 + 16 tanh.f16x2 +
// 32 cvt + 32 FFMA (f32 accumulate — no f16 accumulation risk).
// grid (LXc/64, LYc/64, Bc*2); half 0 -> g_S, half 1 -> g_S2.
// ---------------------------------------------------------------------------
__global__ __launch_bounds__(256) void score_tile_kernel(const float* __restrict__ vm)
{
    const int b    = blockIdx.z >> 1;
    const int half = blockIdx.z & 1;
    const int kb   = half * 128;
    const int y0   = blockIdx.y * 64;
    const int l0   = blockIdx.x * 64;

    __shared__ uint32_t Ys16[2][8][68];   // [buf][kpair][y]  u32 = (y[k0],y[k1])
    __shared__ uint32_t Xs16[2][8][68];   // [buf][kpair][l]
    __shared__ float    Vs[128];

    const int tid = threadIdx.x;
    if (tid < 128) Vs[tid] = vm[kb + tid];

    const int lrow = tid >> 2;           // 0..63: row for fill
    const int f4   = (tid & 3) * 4;      // k offset 0,4,8,12
    const int kp0  = f4 >> 1;            // k-pair base: 0,2,4,6
    const int tx   = tid & 15;
    const int ty   = tid >> 4;

    const float* Yb = g_Yp + (b * LYc + y0) * Hc + kb;
    const float* Xb = g_Xp + (b * LXc + l0) * Hc + kb;

    float acc[4][4] = {};

    // prologue: chunk 0 -> buf 0 (pack own float4 into k-pairs)
    {
        float4 av = *(const float4*)&Yb[lrow * Hc + f4];
        float4 bv = *(const float4*)&Xb[lrow * Hc + f4];
        Ys16[0][kp0 + 0][lrow] = pack_f16x2(av.x, av.y);
        Ys16[0][kp0 + 1][lrow] = pack_f16x2(av.z, av.w);
        Xs16[0][kp0 + 0][lrow] = pack_f16x2(bv.x, bv.y);
        Xs16[0][kp0 + 1][lrow] = pack_f16x2(bv.z, bv.w);
    }
    __syncthreads();

    int buf = 0;
    const int nch = 128 / 16;   // 8 chunks of 16 k (8 k-pairs)
    for (int c = 0; c < nch; c++) {
        float4 av, bv;
        if (c + 1 < nch) {
            const int nk = (c + 1) * 16;
            av = *(const float4*)&Yb[lrow * Hc + nk + f4];
            bv = *(const float4*)&Xb[lrow * Hc + nk + f4];
        }

        #pragma unroll
        for (int kp = 0; kp < 8; kp++) {
            const float v0 = Vs[c * 16 + kp * 2];
            const float v1 = Vs[c * 16 + kp * 2 + 1];
            uint4 yq = *(const uint4*)&Ys16[buf][kp][ty * 4];
            uint4 xq = *(const uint4*)&Xs16[buf][kp][tx * 4];
            const uint32_t ys[4] = {yq.x, yq.y, yq.z, yq.w};
            const uint32_t xs[4] = {xq.x, xq.y, xq.z, xq.w};
            #pragma unroll
            for (int i = 0; i < 4; i++) {
                #pragma unroll
                for (int j = 0; j < 4; j++) {
                    uint32_t t = tanh_f16x2(hsub2(xs[j], ys[i]));
                    float2 f = unpack_f16x2(t);
                    acc[i][j] = fmaf(v0, f.x, fmaf(v1, f.y, acc[i][j]));
                }
            }
        }

        if (c + 1 < nch) {
            const int nb = buf ^ 1;
            Ys16[nb][kp0 + 0][lrow] = pack_f16x2(av.x, av.y);
            Ys16[nb][kp0 + 1][lrow] = pack_f16x2(av.z, av.w);
            Xs16[nb][kp0 + 0][lrow] = pack_f16x2(bv.x, bv.y);
            Xs16[nb][kp0 + 1][lrow] = pack_f16x2(bv.z, bv.w);
            __syncthreads();
            buf = nb;
        }
    }

    float* Sb = (half ? g_S2 : g_S) + (b * LYc + y0) * LXc + l0;
    #pragma unroll
    for (int i = 0; i < 4; i++) {
        float4 st = make_float4(acc[i][0], acc[i][1], acc[i][2], acc[i][3]);
        *(float4*)&Sb[(ty * 4 + i) * LXc + tx * 4] = st;
    }
}

// ---------------------------------------------------------------------------
// Kernel 3: softmax over l (sums split-K partials); writes P bf16 hi/lo.
// ---------------------------------------------------------------------------
__global__ __launch_bounds__(256) void softmax_kernel()
{
    const int b    = blockIdx.y;
    const int y    = blockIdx.x * 8 + (threadIdx.x >> 5);
    const int lane = threadIdx.x & 31;

    const int rbase = (b * LYc + y) * LXc;
    float v[12];
    float mx = -1e30f;
    #pragma unroll
    for (int j = 0; j < 12; j++) {
        const int idx = rbase + lane + 32 * j;
        v[j] = g_S[idx] + g_S2[idx];
        mx = fmaxf(mx, v[j]);
    }
    #pragma unroll
    for (int o = 16; o; o >>= 1)
        mx = fmaxf(mx, __shfl_xor_sync(0xffffffffu, mx, o));
    float sum = 0.f;
    #pragma unroll
    for (int j = 0; j < 12; j++) {
        v[j] = ex2_fast((v[j] - mx) * 1.4426950408889634f);
        sum += v[j];
    }
    #pragma unroll
    for (int o = 16; o; o >>= 1)
        sum += __shfl_xor_sync(0xffffffffu, sum, o);
    float inv = 1.0f / sum;

    #pragma unroll
    for (int j = 0; j < 12; j++) {
        float p = v[j] * inv;
        __nv_bfloat16 h = __float2bfloat16(p);
        __nv_bfloat16 l = __float2bfloat16(p - __bfloat162float(h));
        g_Ph[rbase + lane + 32 * j] = __bfloat16_as_ushort(h);
        g_Pl[rbase + lane + 32 * j] = __bfloat16_as_ushort(l);
    }
}

// ---------------------------------------------------------------------------
extern "C" void kernel_launch(void* const* d_in, const int* in_sizes, int n_in,
                              void* d_out, int out_size)
{
    const float* x  = (const float*)d_in[0];
    const float* y  = (const float*)d_in[1];
    const float* Wm = (const float*)d_in[2];
    const float* vm = (const float*)d_in[3];
    float* out = (float*)d_out;

    const int NTOT4 = (Bc * LXc * Fc + Bc * LYc * Fc + Hc * Fc) / 4;
    conv_split_kernel <<<(NTOT4 + 255) / 256, 256>>>(x, y, Wm);
    transpose_x_kernel<<<dim3(Fc / 32, LXc / 32, Bc), 256>>>(x);
    proj_mma_kernel   <<<dim3(Hc / 64, (LXc * Bc) / 64, 2), 128>>>();
    score_tile_kernel <<<dim3(LXc / 64, LYc / 64, Bc * 2), 256>>>(vm);
    softmax_kernel    <<<dim3(LYc / 8, Bc), 256>>>();
    outgemm_mma_kernel<<<dim3(Fc / 64, LYc / 64, Bc), 128>>>(out);
}

// round 17
// speedup vs baseline: 1.1023x; 1.0004x over previous
#include <cuda_runtime.h>
#include <cuda_bf16.h>
#include <cstdint>

#define Bc  4
#define LXc 384
#define LYc 384
#define Hc  256
#define Fc  512

// scratch (allocation-free rule: __device__ globals)
__device__ float  g_Xp[Bc * LXc * Hc];     // x @ Wm^T (fp32, for score)
__device__ float  g_Yp[Bc * LYc * Hc];     // y @ Wm^T
__device__ float  g_S [Bc * LYc * LXc];    // partial scores, h in [0,128)
__device__ float  g_S2[Bc * LYc * LXc];    // partial scores, h in [128,256)
__device__ ushort g_xh[Bc * LXc * Fc], g_xl[Bc * LXc * Fc];   // x  hi/lo bf16
__device__ ushort g_yh[Bc * LYc * Fc], g_yl[Bc * LYc * Fc];   // y  hi/lo
__device__ ushort g_Wh[Hc * Fc],       g_Wl[Hc * Fc];         // Wm hi/lo
__device__ ushort g_xTh[Bc * Fc * LXc], g_xTl[Bc * Fc * LXc]; // xT hi/lo
__device__ ushort g_Ph[Bc * LYc * LXc], g_Pl[Bc * LYc * LXc]; // softmax P hi/lo

#define GEMM_STAGE_BYTES 20480                 // 4 arrays x 2560 ushorts
#define GEMM_SMEM (3 * GEMM_STAGE_BYTES)       // 61440 B dynamic

__device__ __forceinline__ float ex2_fast(float x) {
    float r; asm("ex2.approx.f32 %0, %1;" : "=f"(r) : "f"(x)); return r;
}
__device__ __forceinline__ uint32_t smem_u32(const void* p) {
    uint32_t a;
    asm("{ .reg .u64 t; cvta.to.shared.u64 t, %1; cvt.u32.u64 %0, t; }"
        : "=r"(a) : "l"(p));
    return a;
}
__device__ __forceinline__ uint32_t packbf(float lo, float hi) {
    uint32_t r;
    asm("cvt.rn.bf16x2.f32 %0, %1, %2;" : "=r"(r) : "f"(hi), "f"(lo));
    return r;
}
__device__ __forceinline__ uint32_t packres(uint32_t h, float lo, float hi) {
    float fl = __uint_as_float(h << 16);
    float fh = __uint_as_float(h & 0xffff0000u);
    return packbf(lo - fl, hi - fh);
}
__device__ __forceinline__ uint32_t pack_f16x2(float lo, float hi) {
    uint32_t r;
    asm("cvt.rn.f16x2.f32 %0, %1, %2;" : "=r"(r) : "f"(hi), "f"(lo));
    return r;
}
__device__ __forceinline__ uint32_t hsub2(uint32_t a, uint32_t b) {
    uint32_t r; asm("sub.f16x2 %0, %1, %2;" : "=r"(r) : "r"(a), "r"(b));
    return r;
}
__device__ __forceinline__ uint32_t tanh_f16x2(uint32_t x) {
    uint32_t r; asm("tanh.approx.f16x2 %0, %1;" : "=r"(r) : "r"(x)); return r;
}
__device__ __forceinline__ float2 unpack_f16x2(uint32_t p) {
    float lo, hi;
    asm("{ .reg .f16 a, b;\n\t"
        "mov.b32 {a, b}, %2;\n\t"
        "cvt.f32.f16 %0, a;\n\t"
        "cvt.f32.f16 %1, b;\n\t}"
        : "=f"(lo), "=f"(hi) : "r"(p));
    return make_float2(lo, hi);
}
__device__ __forceinline__ void ldm4(uint32_t* r, uint32_t a) {
    asm volatile("ldmatrix.sync.aligned.m8n8.x4.shared.b16 {%0,%1,%2,%3}, [%4];"
                 : "=r"(r[0]), "=r"(r[1]), "=r"(r[2]), "=r"(r[3]) : "r"(a));
}
__device__ __forceinline__ void mma16816(float* c, const uint32_t* a,
                                         uint32_t b0, uint32_t b1) {
    asm volatile(
        "mma.sync.aligned.m16n8k16.row.col.f32.bf16.bf16.f32 "
        "{%0,%1,%2,%3}, {%4,%5,%6,%7}, {%8,%9}, {%0,%1,%2,%3};"
        : "+f"(c[0]), "+f"(c[1]), "+f"(c[2]), "+f"(c[3])
        : "r"(a[0]), "r"(a[1]), "r"(a[2]), "r"(a[3]), "r"(b0), "r"(b1));
}
__device__ __forceinline__ void cpa16(uint32_t saddr, const void* g) {
    asm volatile("cp.async.cg.shared.global [%0], [%1], 16;"
                 :: "r"(saddr), "l"(g) : "memory");
}
__device__ __forceinline__ void cpa_commit() {
    asm volatile("cp.async.commit_group;" ::: "memory");
}

// ---------------------------------------------------------------------------
// HMMA GEMM, 3-stage cp.async pipeline (2-deep prefetch, no register staging).
// C[64,64] = A[64,K] @ B[64,K]^T, bf16 hi/lo 3-product, fp32 accum.
// 128 threads, 4 warps (32x32 each). K multiple of 32.
// Dynamic smem 60KB: stage s at dynsm + s*20480; within a stage:
//   AH @ +0, AL @ +5120, BH @ +10240, BL @ +15360  (row stride 40 ushorts).
// MMA/ldmatrix fragment logic identical to validated R12-16 core.
// ---------------------------------------------------------------------------
__device__ void gemm_mma_pre(const ushort* __restrict__ Ah,
                             const ushort* __restrict__ Al, int lda,
                             const ushort* __restrict__ Bh,
                             const ushort* __restrict__ Bl, int ldb,
                             float* __restrict__ C, int ldc, int K)
{
    extern __shared__ char dynsm[];
    const uint32_t sb = smem_u32(dynsm);

    const int tid = threadIdx.x, wid = tid >> 5, lane = tid & 31;
    const int wm = (wid >> 1) * 32, wn = (wid & 1) * 32;
    const int crow = tid >> 1, ckb = (tid & 1) * 16;
    const int cb = (crow * 40 + ckb) * 2;     // byte offset within an array

    const ushort* pAh = Ah + crow * lda + ckb;
    const ushort* pAl = Al + crow * lda + ckb;
    const ushort* pBh = Bh + crow * ldb + ckb;
    const ushort* pBl = Bl + crow * ldb + ckb;

    float c[2][4][4];
    #pragma unroll
    for (int i = 0; i < 2; i++)
        #pragma unroll
        for (int j = 0; j < 4; j++)
            #pragma unroll
            for (int q = 0; q < 4; q++) c[i][j][q] = 0.f;

    const int nch = K >> 5;

    auto load_chunk = [&](int s, int ch) {
        const uint32_t st = sb + s * GEMM_STAGE_BYTES + cb;
        const int nk = ch * 32;
        cpa16(st,                 pAh + nk);
        cpa16(st + 16,            pAh + nk + 8);
        cpa16(st + 5120,          pAl + nk);
        cpa16(st + 5120 + 16,     pAl + nk + 8);
        cpa16(st + 10240,         pBh + nk);
        cpa16(st + 10240 + 16,    pBh + nk + 8);
        cpa16(st + 15360,         pBl + nk);
        cpa16(st + 15360 + 16,    pBl + nk + 8);
        cpa_commit();
    };

    load_chunk(0, 0);
    if (nch > 1) load_chunk(1, 1);

    for (int ch = 0; ch < nch; ch++) {
        if (ch + 1 < nch)
            asm volatile("cp.async.wait_group 1;" ::: "memory");
        else
            asm volatile("cp.async.wait_group 0;" ::: "memory");
        __syncthreads();

        if (ch + 2 < nch) load_chunk((ch + 2) % 3, ch + 2);

        const int s = ch % 3;
        const uint32_t aH0 = sb + s * GEMM_STAGE_BYTES;
        const uint32_t aL0 = aH0 + 5120;
        const uint32_t bH0 = aH0 + 10240;
        const uint32_t bL0 = aH0 + 15360;

        #pragma unroll
        for (int ks = 0; ks < 2; ks++) {
            uint32_t aHf[2][4], aLf[2][4], bHf[2][4], bLf[2][4];
            #pragma unroll
            for (int mt = 0; mt < 2; mt++) {
                const int row = wm + mt * 16 + (lane & 15);
                const int kc  = ks * 16 + (lane >> 4) * 8;
                const uint32_t off = (uint32_t)(row * 40 + kc) * 2;
                ldm4(aHf[mt], aH0 + off);
                ldm4(aLf[mt], aL0 + off);
            }
            #pragma unroll
            for (int g = 0; g < 2; g++) {
                const int row = wn + g * 16 + ((lane >> 4) << 3) + (lane & 7);
                const int kc  = ks * 16 + ((lane >> 3) & 1) * 8;
                const uint32_t off = (uint32_t)(row * 40 + kc) * 2;
                ldm4(bHf[g], bH0 + off);
                ldm4(bLf[g], bL0 + off);
            }
            #pragma unroll
            for (int mt = 0; mt < 2; mt++)
                #pragma unroll
                for (int g = 0; g < 2; g++)
                    #pragma unroll
                    for (int h = 0; h < 2; h++) {
                        float* cf = c[mt][g * 2 + h];
                        mma16816(cf, aHf[mt], bHf[g][2*h], bHf[g][2*h+1]);
                        mma16816(cf, aLf[mt], bHf[g][2*h], bHf[g][2*h+1]);
                        mma16816(cf, aHf[mt], bLf[g][2*h], bLf[g][2*h+1]);
                    }
        }
        __syncthreads();
    }

    #pragma unroll
    for (int mt = 0; mt < 2; mt++) {
        const int r0 = wm + mt * 16 + (lane >> 2);
        #pragma unroll
        for (int nt = 0; nt < 4; nt++) {
            const int cc = wn + nt * 8 + (lane & 3) * 2;
            float* p = C + r0 * ldc + cc;
            *(float2*)p             = make_float2(c[mt][nt][0], c[mt][nt][1]);
            *(float2*)(p + 8 * ldc) = make_float2(c[mt][nt][2], c[mt][nt][3]);
        }
    }
}

// ---------------------------------------------------------------------------
// Kernel A: split x / y / Wm into bf16 hi/lo in global memory (once).
// ---------------------------------------------------------------------------
__global__ __launch_bounds__(256) void conv_split_kernel(
    const float* __restrict__ x, const float* __restrict__ y,
    const float* __restrict__ W)
{
    const int NX4 = Bc * LXc * Fc / 4;
    const int NY4 = Bc * LYc * Fc / 4;
    const int NW4 = Hc * Fc / 4;
    int i4 = blockIdx.x * 256 + threadIdx.x;
    const float* src; ushort* dh; ushort* dl; int o4;
    if (i4 < NX4)            { src = x; dh = g_xh; dl = g_xl; o4 = i4; }
    else if (i4 < NX4 + NY4) { src = y; dh = g_yh; dl = g_yl; o4 = i4 - NX4; }
    else if (i4 < NX4 + NY4 + NW4)
                             { src = W; dh = g_Wh; dl = g_Wl; o4 = i4 - NX4 - NY4; }
    else return;
    float4 v = ((const float4*)src)[o4];
    uint32_t h0 = packbf(v.x, v.y), h1 = packbf(v.z, v.w);
    uint32_t l0 = packres(h0, v.x, v.y), l1 = packres(h1, v.z, v.w);
    ((uint2*)dh)[o4] = make_uint2(h0, h1);
    ((uint2*)dl)[o4] = make_uint2(l0, l1);
}

// ---------------------------------------------------------------------------
// Kernel B: transpose x -> bf16 hi/lo xT[b][f][l]
// ---------------------------------------------------------------------------
__global__ __launch_bounds__(256) void transpose_x_kernel(const float* __restrict__ x)
{
    __shared__ float t[32][33];
    const int b  = blockIdx.z;
    const int f0 = blockIdx.x * 32;
    const int l0 = blockIdx.y * 32;
    const int tx = threadIdx.x & 31;
    const int ty = threadIdx.x >> 5;

    #pragma unroll
    for (int i = ty; i < 32; i += 8)
        t[i][tx] = x[(b * LXc + l0 + i) * Fc + f0 + tx];
    __syncthreads();
    #pragma unroll
    for (int i = ty; i < 32; i += 8) {
        float v = t[tx][i];
        __nv_bfloat16 h = __float2bfloat16(v);
        __nv_bfloat16 l = __float2bfloat16(v - __bfloat162float(h));
        const int idx = (b * Fc + f0 + i) * LXc + l0 + tx;
        g_xTh[idx] = __bfloat16_as_ushort(h);
        g_xTl[idx] = __bfloat16_as_ushort(l);
    }
}

// ---------------------------------------------------------------------------
// Kernel 1: proj.  grid (Hc/64=4, 1536/64=24, 2)
// ---------------------------------------------------------------------------
__global__ __launch_bounds__(128) void proj_mma_kernel()
{
    const ushort* Ah = blockIdx.z ? g_yh : g_xh;
    const ushort* Al = blockIdx.z ? g_yl : g_xl;
    float*        Out = blockIdx.z ? g_Yp : g_Xp;
    gemm_mma_pre(Ah + blockIdx.y * 64 * Fc, Al + blockIdx.y * 64 * Fc, Fc,
                 g_Wh + blockIdx.x * 64 * Fc, g_Wl + blockIdx.x * 64 * Fc, Fc,
                 Out + blockIdx.y * 64 * Hc + blockIdx.x * 64, Hc, Fc);
}

// ---------------------------------------------------------------------------
// Kernel 4: outgemm.  grid (Fc/64=8, LYc/64=6, Bc)
// ---------------------------------------------------------------------------
__global__ __launch_bounds__(128) void outgemm_mma_kernel(float* __restrict__ out)
{
    const int b = blockIdx.z;
    gemm_mma_pre(g_Ph  + (b * LYc + blockIdx.y * 64) * LXc,
                 g_Pl  + (b * LYc + blockIdx.y * 64) * LXc, LXc,
                 g_xTh + (b * Fc + blockIdx.x * 64) * LXc,
                 g_xTl + (b * Fc + blockIdx.x * 64) * LXc, LXc,
                 out + (b * LYc + blockIdx.y * 64) * Fc + blockIdx.x * 64,
                 Fc, LXc);
}

// ---------------------------------------------------------------------------
// Kernel 2: tanh-score, split-K over h, f16x2 front half (validated R16;
// at the MUFU tanh floor — unchanged).
// ---------------------------------------------------------------------------
__global__ __launch_bounds__(256) void score_tile_kernel(const float* __restrict__ vm)
{
    const int b    = blockIdx.z >> 1;
    const int half = blockIdx.z & 1;
    const int kb   = half * 128;
    const int y0   = blockIdx.y * 64;
    const int l0   = blockIdx.x * 64;

    __shared__ uint32_t Ys16[2][8][68];
    __shared__ uint32_t Xs16[2][8][68];
    __shared__ float    Vs[128];

    const int tid = threadIdx.x;
    if (tid < 128) Vs[tid] = vm[kb + tid];

    const int lrow = tid >> 2;
    const int f4   = (tid & 3) * 4;
    const int kp0  = f4 >> 1;
    const int tx   = tid & 15;
    const int ty   = tid >> 4;

    const float* Yb = g_Yp + (b * LYc + y0) * Hc + kb;
    const float* Xb = g_Xp + (b * LXc + l0) * Hc + kb;

    float acc[4][4] = {};

    {
        float4 av = *(const float4*)&Yb[lrow * Hc + f4];
        float4 bv = *(const float4*)&Xb[lrow * Hc + f4];
        Ys16[0][kp0 + 0][lrow] = pack_f16x2(av.x, av.y);
        Ys16[0][kp0 + 1][lrow] = pack_f16x2(av.z, av.w);
        Xs16[0][kp0 + 0][lrow] = pack_f16x2(bv.x, bv.y);
        Xs16[0][kp0 + 1][lrow] = pack_f16x2(bv.z, bv.w);
    }
    __syncthreads();

    int buf = 0;
    const int nch = 128 / 16;
    for (int c = 0; c < nch; c++) {
        float4 av, bv;
        if (c + 1 < nch) {
            const int nk = (c + 1) * 16;
            av = *(const float4*)&Yb[lrow * Hc + nk + f4];
            bv = *(const float4*)&Xb[lrow * Hc + nk + f4];
        }

        #pragma unroll
        for (int kp = 0; kp < 8; kp++) {
            const float v0 = Vs[c * 16 + kp * 2];
            const float v1 = Vs[c * 16 + kp * 2 + 1];
            uint4 yq = *(const uint4*)&Ys16[buf][kp][ty * 4];
            uint4 xq = *(const uint4*)&Xs16[buf][kp][tx * 4];
            const uint32_t ys[4] = {yq.x, yq.y, yq.z, yq.w};
            const uint32_t xs[4] = {xq.x, xq.y, xq.z, xq.w};
            #pragma unroll
            for (int i = 0; i < 4; i++) {
                #pragma unroll
                for (int j = 0; j < 4; j++) {
                    uint32_t t = tanh_f16x2(hsub2(xs[j], ys[i]));
                    float2 f = unpack_f16x2(t);
                    acc[i][j] = fmaf(v0, f.x, fmaf(v1, f.y, acc[i][j]));
                }
            }
        }

        if (c + 1 < nch) {
            const int nb = buf ^ 1;
            Ys16[nb][kp0 + 0][lrow] = pack_f16x2(av.x, av.y);
            Ys16[nb][kp0 + 1][lrow] = pack_f16x2(av.z, av.w);
            Xs16[nb][kp0 + 0][lrow] = pack_f16x2(bv.x, bv.y);
            Xs16[nb][kp0 + 1][lrow] = pack_f16x2(bv.z, bv.w);
            __syncthreads();
            buf = nb;
        }
    }

    float* Sb = (half ? g_S2 : g_S) + (b * LYc + y0) * LXc + l0;
    #pragma unroll
    for (int i = 0; i < 4; i++) {
        float4 st = make_float4(acc[i][0], acc[i][1], acc[i][2], acc[i][3]);
        *(float4*)&Sb[(ty * 4 + i) * LXc + tx * 4] = st;
    }
}

// ---------------------------------------------------------------------------
// Kernel 3: softmax over l (sums split-K partials); writes P bf16 hi/lo.
// ---------------------------------------------------------------------------
__global__ __launch_bounds__(256) void softmax_kernel()
{
    const int b    = blockIdx.y;
    const int y    = blockIdx.x * 8 + (threadIdx.x >> 5);
    const int lane = threadIdx.x & 31;

    const int rbase = (b * LYc + y) * LXc;
    float v[12];
    float mx = -1e30f;
    #pragma unroll
    for (int j = 0; j < 12; j++) {
        const int idx = rbase + lane + 32 * j;
        v[j] = g_S[idx] + g_S2[idx];
        mx = fmaxf(mx, v[j]);
    }
    #pragma unroll
    for (int o = 16; o; o >>= 1)
        mx = fmaxf(mx, __shfl_xor_sync(0xffffffffu, mx, o));
    float sum = 0.f;
    #pragma unroll
    for (int j = 0; j < 12; j++) {
        v[j] = ex2_fast((v[j] - mx) * 1.4426950408889634f);
        sum += v[j];
    }
    #pragma unroll
    for (int o = 16; o; o >>= 1)
        sum += __shfl_xor_sync(0xffffffffu, sum, o);
    float inv = 1.0f / sum;

    #pragma unroll
    for (int j = 0; j < 12; j++) {
        float p = v[j] * inv;
        __nv_bfloat16 h = __float2bfloat16(p);
        __nv_bfloat16 l = __float2bfloat16(p - __bfloat162float(h));
        g_Ph[rbase + lane + 32 * j] = __bfloat16_as_ushort(h);
        g_Pl[rbase + lane + 32 * j] = __bfloat16_as_ushort(l);
    }
}

// ---------------------------------------------------------------------------
extern "C" void kernel_launch(void* const* d_in, const int* in_sizes, int n_in,
                              void* d_out, int out_size)
{
    const float* x  = (const float*)d_in[0];
    const float* y  = (const float*)d_in[1];
    const float* Wm = (const float*)d_in[2];
    const float* vm = (const float*)d_in[3];
    float* out = (float*)d_out;

    cudaFuncSetAttribute(proj_mma_kernel,
                         cudaFuncAttributeMaxDynamicSharedMemorySize, GEMM_SMEM);
    cudaFuncSetAttribute(outgemm_mma_kernel,
                         cudaFuncAttributeMaxDynamicSharedMemorySize, GEMM_SMEM);

    const int NTOT4 = (Bc * LXc * Fc + Bc * LYc * Fc + Hc * Fc) / 4;
    conv_split_kernel <<<(NTOT4 + 255) / 256, 256>>>(x, y, Wm);
    transpose_x_kernel<<<dim3(Fc / 32, LXc / 32, Bc), 256>>>(x);
    proj_mma_kernel   <<<dim3(Hc / 64, (LXc * Bc) / 64, 2), 128, GEMM_SMEM>>>();
    score_tile_kernel <<<dim3(LXc / 64, LYc / 64, Bc * 2), 256>>>(vm);
    softmax_kernel    <<<dim3(LYc / 8, Bc), 256>>>();
    outgemm_mma_kernel<<<dim3(Fc / 64, LYc / 64, Bc), 128, GEMM_SMEM>>>(out);
}